// round 3
// baseline (speedup 1.0000x reference)
#include <cuda_runtime.h>
#include <cstdint>

// Problem constants
#define BB    8
#define NN    65536
#define NPTS  (BB*NN)           // 524288
#define GSIZE (1<<21)           // 128^3 cells per batch
#define GTOT  (BB*GSIZE)        // 16,777,216

// ---------------- device scratch (static, no allocation) ----------------
__device__ int      g_grid[GTOT];            // occupancy -> slot map (or -1)
__device__ int      g_bsum[4096];            // scan block sums (512 per batch)
__device__ int      g_Mb[BB];                // valid voxel count per batch
__device__ int      g_nvalid;                // total valid
__device__ int      g_code[NPTS];            // per-point compact voxel code
__device__ int      g_inv[NPTS];             // per-point slot
__device__ int      g_slotcode[NPTS];        // slot -> compact code
__device__ float    g_cnt[NPTS];             // per-voxel masked point count
__device__ float    g_vfeat[(size_t)NPTS*16];
__device__ int      g_nbr[(size_t)NPTS*27];  // neighbor slot table
__device__ float    g_h1[(size_t)NPTS*32];
__device__ float    g_h2[(size_t)NPTS*64];
__device__ float    g_h3[(size_t)NPTS*128];
__device__ unsigned g_obits[3];              // origin (uint-encoded fp32 min)
__device__ double   g_sum[128], g_sumsq[128];
__device__ float    g_scale[128], g_shift[128];

// ---------------- helpers ----------------
__device__ __forceinline__ int blockExclScan(int val, int &total, int nwarps) {
    int lane = threadIdx.x & 31, wid = threadIdx.x >> 5;
    int v = val;
#pragma unroll
    for (int o = 1; o < 32; o <<= 1) {
        int t = __shfl_up_sync(0xffffffffu, v, o);
        if (lane >= o) v += t;
    }
    __shared__ int ws[32];
    if (lane == 31) ws[wid] = v;
    __syncthreads();
    if (wid == 0) {
        int w = (lane < nwarps) ? ws[lane] : 0;
#pragma unroll
        for (int o = 1; o < 32; o <<= 1) {
            int t = __shfl_up_sync(0xffffffffu, w, o);
            if (lane >= o) w += t;
        }
        ws[lane] = w;
    }
    __syncthreads();
    int warpoff = wid ? ws[wid - 1] : 0;
    total = ws[nwarps - 1];
    return warpoff + v - val;   // exclusive prefix
}

// ---------------- kernels ----------------
__global__ void k_zero() {
    size_t i = (size_t)blockIdx.x * blockDim.x + threadIdx.x;
    size_t stride = (size_t)gridDim.x * blockDim.x;
    for (size_t j = i; j < (size_t)GTOT; j += stride) g_grid[j] = 0;
    for (size_t j = i; j < (size_t)NPTS; j += stride) g_cnt[j] = 0.f;
    for (size_t j = i; j < (size_t)NPTS * 16; j += stride) g_vfeat[j] = 0.f;
    if (i < 3) g_obits[i] = 0x7F7FFFFFu;  // +FLT_MAX bits
}

__global__ void k_min(const float* __restrict__ xyz) {
    float mn0 = 3.4e38f, mn1 = 3.4e38f, mn2 = 3.4e38f;
    for (int i = blockIdx.x * blockDim.x + threadIdx.x; i < NPTS;
         i += gridDim.x * blockDim.x) {
        mn0 = fminf(mn0, xyz[3 * i + 0]);
        mn1 = fminf(mn1, xyz[3 * i + 1]);
        mn2 = fminf(mn2, xyz[3 * i + 2]);
    }
#pragma unroll
    for (int o = 16; o; o >>= 1) {
        mn0 = fminf(mn0, __shfl_down_sync(0xffffffffu, mn0, o));
        mn1 = fminf(mn1, __shfl_down_sync(0xffffffffu, mn1, o));
        mn2 = fminf(mn2, __shfl_down_sync(0xffffffffu, mn2, o));
    }
    __shared__ float s[3][8];
    int lane = threadIdx.x & 31, wid = threadIdx.x >> 5;
    if (lane == 0) { s[0][wid] = mn0; s[1][wid] = mn1; s[2][wid] = mn2; }
    __syncthreads();
    if (threadIdx.x == 0) {
        float a = s[0][0], b = s[1][0], c = s[2][0];
        for (int w = 1; w < 8; w++) {
            a = fminf(a, s[0][w]); b = fminf(b, s[1][w]); c = fminf(c, s[2][w]);
        }
        atomicMin(&g_obits[0], __float_as_uint(a));
        atomicMin(&g_obits[1], __float_as_uint(b));
        atomicMin(&g_obits[2], __float_as_uint(c));
    }
}

__global__ void k_codes(const float* __restrict__ xyz) {
    int i = blockIdx.x * blockDim.x + threadIdx.x;
    if (i >= NPTS) return;
    int b = i / NN;
    float ox = __uint_as_float(g_obits[0]);
    float oy = __uint_as_float(g_obits[1]);
    float oz = __uint_as_float(g_obits[2]);
    // IEEE division to bit-match the reference's (xyz-origin)/0.4f
    int vx = (int)__fdiv_rn(xyz[3 * i + 0] - ox, 0.4f);
    int vy = (int)__fdiv_rn(xyz[3 * i + 1] - oy, 0.4f);
    int vz = (int)__fdiv_rn(xyz[3 * i + 2] - oz, 0.4f);
    vx = min(127, max(0, vx)); vy = min(127, max(0, vy)); vz = min(127, max(0, vz));
    int code = vx | (vy << 7) | (vz << 14);
    g_code[i] = code;
    g_grid[(size_t)b * GSIZE + code] = 1;
}

__global__ void k_scanA() {
    int base = blockIdx.x * 4096 + threadIdx.x * 4;
    int s = g_grid[base] + g_grid[base + 1] + g_grid[base + 2] + g_grid[base + 3];
    int tot;
    blockExclScan(s, tot, 32);
    if (threadIdx.x == 0) g_bsum[blockIdx.x] = tot;
}

__global__ void k_scanB() {
    int b = blockIdx.x, t = threadIdx.x;
    int v = g_bsum[b * 512 + t];
    int tot;
    int excl = blockExclScan(v, tot, 16);
    g_bsum[b * 512 + t] = excl;
    if (t == 511) g_Mb[b] = tot;
}

__global__ void k_sumMb() {
    if (threadIdx.x == 0) {
        int s = 0;
        for (int b = 0; b < BB; b++) s += g_Mb[b];
        g_nvalid = s;
    }
}

__global__ void k_scanC() {
    int blk = blockIdx.x;
    int b = blk >> 9;                       // / 512
    int cbase = (blk & 511) * 4096 + threadIdx.x * 4;   // cell idx within batch
    size_t gbase = (size_t)b * GSIZE + cbase;
    int o0 = g_grid[gbase + 0], o1 = g_grid[gbase + 1];
    int o2 = g_grid[gbase + 2], o3 = g_grid[gbase + 3];
    int s = o0 + o1 + o2 + o3;
    int tot;
    int excl = blockExclScan(s, tot, 32);
    int run = g_bsum[blk] + excl;
    int occ[4] = {o0, o1, o2, o3};
#pragma unroll
    for (int j = 0; j < 4; j++) {
        if (occ[j]) {
            g_grid[gbase + j] = run;
            g_slotcode[b * NN + run] = cbase + j;
            run++;
        } else {
            g_grid[gbase + j] = -1;
        }
    }
}

__global__ void k_aggregate(const float* __restrict__ feat,
                            const float* __restrict__ mask) {
    int i = blockIdx.x * blockDim.x + threadIdx.x;
    if (i >= NPTS) return;
    int b = i / NN;
    int code = g_code[i];
    int slot = g_grid[(size_t)b * GSIZE + code];
    g_inv[i] = slot;
    float m = mask[i];
    if (m != 0.f) {
        int row = b * NN + slot;
        atomicAdd(&g_cnt[row], m);
        const float* f = feat + (size_t)i * 16;
        float* dst = g_vfeat + (size_t)row * 16;
#pragma unroll
        for (int c = 0; c < 16; c++) atomicAdd(&dst[c], f[c] * m);
    }
}

__global__ void k_vnorm() {
    int i = blockIdx.x * blockDim.x + threadIdx.x;
    if (i >= NPTS) return;
    int b = i / NN, slot = i - b * NN;
    if (slot >= g_Mb[b]) return;
    float inv = 1.f / fmaxf(g_cnt[i], 1.f);
    float* r = g_vfeat + (size_t)i * 16;
#pragma unroll
    for (int c = 0; c < 16; c++) r[c] *= inv;
}

__global__ void k_nbr() {
    int slot = blockIdx.x * blockDim.x + threadIdx.x;
    int b = blockIdx.y;
    if (slot >= g_Mb[b]) return;
    int code = g_slotcode[b * NN + slot];
    int x = code & 127, y = (code >> 7) & 127, z = code >> 14;
    const int* grid = g_grid + (size_t)b * GSIZE;
    int* dst = g_nbr + ((size_t)(b * NN + slot)) * 27;
    int ko = 0;
    for (int dz = -1; dz <= 1; dz++)
        for (int dy = -1; dy <= 1; dy++)
            for (int dx = -1; dx <= 1; dx++, ko++) {
                int nx = x + dx, ny = y + dy, nz = z + dz;
                int r = -1;
                if ((unsigned)nx < 128u && (unsigned)ny < 128u && (unsigned)nz < 128u)
                    r = grid[nx | (ny << 7) | (nz << 14)];
                dst[ko] = r;
            }
}

// ---------------- gather-GEMM conv: tile 128 voxels x COUT ----------------
template <int CIN, int COUT, bool BN>
__global__ void __launch_bounds__(256, 1)
conv_kernel(const float* __restrict__ fin, float* __restrict__ fout,
            const float* __restrict__ W, const float* __restrict__ bias) {
    constexpr int TV  = 128;
    constexpr int CPT = COUT / 16;   // outputs per thread (co dim)
    constexpr int VPT = 8;           // voxels per thread
    constexpr int HC  = CIN / 2;
    extern __shared__ float smem[];
    float* Ws = smem;                 // [CIN*COUT]
    float* Xs = smem + CIN * COUT;    // [TV*(CIN+1)] padded

    int b  = blockIdx.y;
    int Mb = g_Mb[b];
    int v0 = blockIdx.x * TV;
    if (v0 >= Mb) return;

    int tid = threadIdx.x;
    int tx = tid & 15, ty = tid >> 4;

    float acc[VPT][CPT];
#pragma unroll
    for (int i = 0; i < VPT; i++)
#pragma unroll
        for (int j = 0; j < CPT; j++) acc[i][j] = 0.f;

    int vg = tid >> 1, half = tid & 1;
    int vidx = v0 + vg;
    bool vok = vidx < Mb;
    const int* nbrp = g_nbr + ((size_t)(b * NN + (vok ? vidx : 0))) * 27;

    for (int ko = 0; ko < 27; ko++) {
        __syncthreads();  // previous tile fully consumed
        for (int e = tid; e < CIN * COUT; e += 256)
            Ws[e] = W[ko * CIN * COUT + e];
        int nbr = vok ? nbrp[ko] : -1;
        float* xdst = Xs + vg * (CIN + 1) + half * HC;
        if (nbr >= 0) {
            const float* src = fin + ((size_t)(b * NN + nbr)) * CIN + half * HC;
#pragma unroll
            for (int c = 0; c < HC; c++) {
                float xv = __ldg(&src[c]);
                if (BN) {
                    int ci = half * HC + c;
                    xv = fmaxf(fmaf(xv, g_scale[ci], g_shift[ci]), 0.f);
                }
                xdst[c] = xv;
            }
        } else {
#pragma unroll
            for (int c = 0; c < HC; c++) xdst[c] = 0.f;
        }
        __syncthreads();
#pragma unroll 4
        for (int ci = 0; ci < CIN; ci++) {
            float xv[VPT], wv[CPT];
#pragma unroll
            for (int i = 0; i < VPT; i++)
                xv[i] = Xs[(ty * VPT + i) * (CIN + 1) + ci];
#pragma unroll
            for (int j = 0; j < CPT; j++)
                wv[j] = Ws[ci * COUT + tx + 16 * j];
#pragma unroll
            for (int i = 0; i < VPT; i++)
#pragma unroll
                for (int j = 0; j < CPT; j++)
                    acc[i][j] = fmaf(xv[i], wv[j], acc[i][j]);
        }
    }
#pragma unroll
    for (int i = 0; i < VPT; i++) {
        int v = v0 + ty * VPT + i;
        if (v < Mb) {
            float* dst = fout + ((size_t)(b * NN + v)) * COUT;
#pragma unroll
            for (int j = 0; j < CPT; j++)
                dst[tx + 16 * j] = acc[i][j] + bias[tx + 16 * j];
        }
    }
}

__global__ void k_zero_stats() {
    int t = threadIdx.x;
    if (t < 128) { g_sum[t] = 0.0; g_sumsq[t] = 0.0; }
}

template <int COUT>
__global__ void k_stats(const float* __restrict__ f) {
    constexpr int RP = 256 / COUT;
    int b = blockIdx.y;
    int Mb = g_Mb[b];
    int tid = threadIdx.x;
    int c = tid % COUT, r0 = tid / COUT;
    float s = 0.f, s2 = 0.f;
    for (int v = blockIdx.x * RP + r0; v < Mb; v += gridDim.x * RP) {
        float x = f[((size_t)(b * NN + v)) * COUT + c];
        s += x;
        s2 = fmaf(x, x, s2);
    }
    __shared__ float sh[256], sh2[256];
    sh[tid] = s; sh2[tid] = s2;
    __syncthreads();
    for (int st = 128; st >= COUT; st >>= 1) {
        if (tid < st) { sh[tid] += sh[tid + st]; sh2[tid] += sh2[tid + st]; }
        __syncthreads();
    }
    if (tid < COUT) {
        atomicAdd(&g_sum[tid], (double)sh[tid]);
        atomicAdd(&g_sumsq[tid], (double)sh2[tid]);
    }
}

template <int COUT>
__global__ void k_finalize(const float* __restrict__ gamma,
                           const float* __restrict__ beta) {
    int c = threadIdx.x;
    if (c >= COUT) return;
    double n = (double)g_nvalid;
    if (n < 1.0) n = 1.0;
    double mean = g_sum[c] / n;
    double var = g_sumsq[c] / n - mean * mean;
    if (var < 0.0) var = 0.0;
    float a = (float)((double)gamma[c] / sqrt(var + 1e-5));
    g_scale[c] = a;
    g_shift[c] = beta[c] - (float)mean * a;
}

__global__ void k_final(const float* __restrict__ mask, float* __restrict__ out) {
    size_t e = (size_t)blockIdx.x * blockDim.x + threadIdx.x;
    if (e >= (size_t)NPTS * 128) return;
    int i = (int)(e >> 7);
    int c = (int)(e & 127);
    int b = i / NN;
    int slot = g_inv[i];
    float h = g_h3[((size_t)(b * NN + slot)) * 128 + c];
    float y = fmaxf(fmaf(h, g_scale[c], g_shift[c]), 0.f);
    out[e] = y * mask[i];
}

// ---------------- host ----------------
extern "C" void kernel_launch(void* const* d_in, const int* in_sizes, int n_in,
                              void* d_out, int out_size) {
    const float* xyz  = (const float*)d_in[0];
    const float* feat = (const float*)d_in[1];
    const float* mask = (const float*)d_in[2];
    const float* W1 = (const float*)d_in[3];
    const float* b1 = (const float*)d_in[4];
    const float* g1 = (const float*)d_in[5];
    const float* be1 = (const float*)d_in[6];
    const float* W2 = (const float*)d_in[7];
    const float* b2 = (const float*)d_in[8];
    const float* g2 = (const float*)d_in[9];
    const float* be2 = (const float*)d_in[10];
    const float* W3 = (const float*)d_in[11];
    const float* b3 = (const float*)d_in[12];
    const float* g3 = (const float*)d_in[13];
    const float* be3 = (const float*)d_in[14];
    float* out = (float*)d_out;

    void *pv = nullptr, *p1 = nullptr, *p2 = nullptr, *p3 = nullptr;
    cudaGetSymbolAddress(&pv, g_vfeat);
    cudaGetSymbolAddress(&p1, g_h1);
    cudaGetSymbolAddress(&p2, g_h2);
    cudaGetSymbolAddress(&p3, g_h3);

    size_t sm1 = (size_t)(16 * 32 + 128 * 17) * sizeof(float);   // 10.6 KB
    size_t sm2 = (size_t)(32 * 64 + 128 * 33) * sizeof(float);   // 24.9 KB
    size_t sm3 = (size_t)(64 * 128 + 128 * 65) * sizeof(float);  // 64.5 KB
    cudaFuncSetAttribute(conv_kernel<64, 128, true>,
                         cudaFuncAttributeMaxDynamicSharedMemorySize, (int)sm3);

    k_zero<<<2048, 256>>>();
    k_min<<<512, 256>>>(xyz);
    k_codes<<<NPTS / 256, 256>>>(xyz);
    k_scanA<<<4096, 1024>>>();
    k_scanB<<<8, 512>>>();
    k_sumMb<<<1, 32>>>();
    k_scanC<<<4096, 1024>>>();
    k_aggregate<<<NPTS / 256, 256>>>(feat, mask);
    k_vnorm<<<NPTS / 256, 256>>>();
    k_nbr<<<dim3(NN / 128, BB), 128>>>();

    dim3 cgrid(NN / 128, BB);

    // layer 1: vfeat(16) -> h1(32), no input affine
    conv_kernel<16, 32, false><<<cgrid, 256, sm1>>>((const float*)pv, (float*)p1, W1, b1);
    k_zero_stats<<<1, 128>>>();
    k_stats<32><<<dim3(64, BB), 256>>>((const float*)p1);
    k_finalize<32><<<1, 32>>>(g1, be1);

    // layer 2: h1(32) -> h2(64), input = relu(bn1(h1))
    conv_kernel<32, 64, true><<<cgrid, 256, sm2>>>((const float*)p1, (float*)p2, W2, b2);
    k_zero_stats<<<1, 128>>>();
    k_stats<64><<<dim3(64, BB), 256>>>((const float*)p2);
    k_finalize<64><<<1, 64>>>(g2, be2);

    // layer 3: h2(64) -> h3(128), input = relu(bn2(h2))
    conv_kernel<64, 128, true><<<cgrid, 256, sm3>>>((const float*)p2, (float*)p3, W3, b3);
    k_zero_stats<<<1, 128>>>();
    k_stats<128><<<dim3(64, BB), 256>>>((const float*)p3);
    k_finalize<128><<<1, 128>>>(g3, be3);

    // scatter: out[point] = relu(bn3(h3[inv])) * mask
    k_final<<<(NPTS * 128) / 256, 256>>>(mask, out);
}

// round 4
// speedup vs baseline: 1.2663x; 1.2663x over previous
#include <cuda_runtime.h>
#include <cstdint>

// Problem constants
#define BB    8
#define NN    65536
#define NPTS  (BB*NN)           // 524288
#define GSIZE (1<<21)           // 128^3 cells per batch
#define GTOT  (BB*GSIZE)        // 16,777,216

// ---------------- device scratch (static, no allocation) ----------------
__device__ int      g_grid[GTOT];            // occupancy -> slot map (or -1)
__device__ int      g_bsum[4096];            // scan block sums (512 per batch)
__device__ int      g_Mb[BB];                // valid voxel count per batch
__device__ int      g_nvalid;                // total valid
__device__ int      g_code[NPTS];            // per-point compact voxel code
__device__ int      g_inv[NPTS];             // per-point slot
__device__ int      g_slotcode[NPTS];        // slot -> compact code
__device__ float    g_cnt[NPTS];             // per-voxel masked point count
__device__ float    g_vfeat[(size_t)NPTS*16];
__device__ int      g_nbr[(size_t)NPTS*27];  // neighbor slot table
__device__ float    g_h1[(size_t)NPTS*32];
__device__ float    g_h2[(size_t)NPTS*64];
__device__ float    g_h3[(size_t)NPTS*128];
__device__ unsigned g_obits[3];              // origin (uint-encoded fp32 min)
__device__ double   g_sum[128], g_sumsq[128];
__device__ float    g_scale[128], g_shift[128];

// ---------------- helpers ----------------
__device__ __forceinline__ int blockExclScan(int val, int &total, int nwarps) {
    int lane = threadIdx.x & 31, wid = threadIdx.x >> 5;
    int v = val;
#pragma unroll
    for (int o = 1; o < 32; o <<= 1) {
        int t = __shfl_up_sync(0xffffffffu, v, o);
        if (lane >= o) v += t;
    }
    __shared__ int ws[32];
    if (lane == 31) ws[wid] = v;
    __syncthreads();
    if (wid == 0) {
        int w = (lane < nwarps) ? ws[lane] : 0;
#pragma unroll
        for (int o = 1; o < 32; o <<= 1) {
            int t = __shfl_up_sync(0xffffffffu, w, o);
            if (lane >= o) w += t;
        }
        ws[lane] = w;
    }
    __syncthreads();
    int warpoff = wid ? ws[wid - 1] : 0;
    total = ws[nwarps - 1];
    return warpoff + v - val;   // exclusive prefix
}

// packed fp32x2 FMA (sm_103a FFMA2) — two exact IEEE fp32 FMAs per issue slot
__device__ __forceinline__ unsigned long long ld64s(const float* p) {
    return *reinterpret_cast<const unsigned long long*>(p);
}
__device__ __forceinline__ void ffma2(unsigned long long& d,
                                      unsigned long long a,
                                      unsigned long long b) {
    asm("fma.rn.f32x2 %0, %1, %2, %0;" : "+l"(d) : "l"(a), "l"(b));
}

// ---------------- kernels ----------------
__global__ void k_zero() {
    size_t i = (size_t)blockIdx.x * blockDim.x + threadIdx.x;
    size_t stride = (size_t)gridDim.x * blockDim.x;
    for (size_t j = i; j < (size_t)GTOT; j += stride) g_grid[j] = 0;
    for (size_t j = i; j < (size_t)NPTS; j += stride) g_cnt[j] = 0.f;
    for (size_t j = i; j < (size_t)NPTS * 16; j += stride) g_vfeat[j] = 0.f;
    if (i < 3) g_obits[i] = 0x7F7FFFFFu;  // +FLT_MAX bits
}

__global__ void k_min(const float* __restrict__ xyz) {
    float mn0 = 3.4e38f, mn1 = 3.4e38f, mn2 = 3.4e38f;
    for (int i = blockIdx.x * blockDim.x + threadIdx.x; i < NPTS;
         i += gridDim.x * blockDim.x) {
        mn0 = fminf(mn0, xyz[3 * i + 0]);
        mn1 = fminf(mn1, xyz[3 * i + 1]);
        mn2 = fminf(mn2, xyz[3 * i + 2]);
    }
#pragma unroll
    for (int o = 16; o; o >>= 1) {
        mn0 = fminf(mn0, __shfl_down_sync(0xffffffffu, mn0, o));
        mn1 = fminf(mn1, __shfl_down_sync(0xffffffffu, mn1, o));
        mn2 = fminf(mn2, __shfl_down_sync(0xffffffffu, mn2, o));
    }
    __shared__ float s[3][8];
    int lane = threadIdx.x & 31, wid = threadIdx.x >> 5;
    if (lane == 0) { s[0][wid] = mn0; s[1][wid] = mn1; s[2][wid] = mn2; }
    __syncthreads();
    if (threadIdx.x == 0) {
        float a = s[0][0], b = s[1][0], c = s[2][0];
        for (int w = 1; w < 8; w++) {
            a = fminf(a, s[0][w]); b = fminf(b, s[1][w]); c = fminf(c, s[2][w]);
        }
        atomicMin(&g_obits[0], __float_as_uint(a));
        atomicMin(&g_obits[1], __float_as_uint(b));
        atomicMin(&g_obits[2], __float_as_uint(c));
    }
}

__global__ void k_codes(const float* __restrict__ xyz) {
    int i = blockIdx.x * blockDim.x + threadIdx.x;
    if (i >= NPTS) return;
    int b = i / NN;
    float ox = __uint_as_float(g_obits[0]);
    float oy = __uint_as_float(g_obits[1]);
    float oz = __uint_as_float(g_obits[2]);
    // IEEE division to bit-match the reference's (xyz-origin)/0.4f
    int vx = (int)__fdiv_rn(xyz[3 * i + 0] - ox, 0.4f);
    int vy = (int)__fdiv_rn(xyz[3 * i + 1] - oy, 0.4f);
    int vz = (int)__fdiv_rn(xyz[3 * i + 2] - oz, 0.4f);
    vx = min(127, max(0, vx)); vy = min(127, max(0, vy)); vz = min(127, max(0, vz));
    int code = vx | (vy << 7) | (vz << 14);
    g_code[i] = code;
    g_grid[(size_t)b * GSIZE + code] = 1;
}

__global__ void k_scanA() {
    int base = blockIdx.x * 4096 + threadIdx.x * 4;
    int s = g_grid[base] + g_grid[base + 1] + g_grid[base + 2] + g_grid[base + 3];
    int tot;
    blockExclScan(s, tot, 32);
    if (threadIdx.x == 0) g_bsum[blockIdx.x] = tot;
}

__global__ void k_scanB() {
    int b = blockIdx.x, t = threadIdx.x;
    int v = g_bsum[b * 512 + t];
    int tot;
    int excl = blockExclScan(v, tot, 16);
    g_bsum[b * 512 + t] = excl;
    if (t == 511) g_Mb[b] = tot;
}

__global__ void k_sumMb() {
    if (threadIdx.x == 0) {
        int s = 0;
        for (int b = 0; b < BB; b++) s += g_Mb[b];
        g_nvalid = s;
    }
}

__global__ void k_scanC() {
    int blk = blockIdx.x;
    int b = blk >> 9;                       // / 512
    int cbase = (blk & 511) * 4096 + threadIdx.x * 4;   // cell idx within batch
    size_t gbase = (size_t)b * GSIZE + cbase;
    int o0 = g_grid[gbase + 0], o1 = g_grid[gbase + 1];
    int o2 = g_grid[gbase + 2], o3 = g_grid[gbase + 3];
    int s = o0 + o1 + o2 + o3;
    int tot;
    int excl = blockExclScan(s, tot, 32);
    int run = g_bsum[blk] + excl;
    int occ[4] = {o0, o1, o2, o3};
#pragma unroll
    for (int j = 0; j < 4; j++) {
        if (occ[j]) {
            g_grid[gbase + j] = run;
            g_slotcode[b * NN + run] = cbase + j;
            run++;
        } else {
            g_grid[gbase + j] = -1;
        }
    }
}

__global__ void k_aggregate(const float* __restrict__ feat,
                            const float* __restrict__ mask) {
    int i = blockIdx.x * blockDim.x + threadIdx.x;
    if (i >= NPTS) return;
    int b = i / NN;
    int code = g_code[i];
    int slot = g_grid[(size_t)b * GSIZE + code];
    g_inv[i] = slot;
    float m = mask[i];
    if (m != 0.f) {
        int row = b * NN + slot;
        atomicAdd(&g_cnt[row], m);
        const float* f = feat + (size_t)i * 16;
        float* dst = g_vfeat + (size_t)row * 16;
#pragma unroll
        for (int c = 0; c < 16; c++) atomicAdd(&dst[c], f[c] * m);
    }
}

__global__ void k_vnorm() {
    int i = blockIdx.x * blockDim.x + threadIdx.x;
    if (i >= NPTS) return;
    int b = i / NN, slot = i - b * NN;
    if (slot >= g_Mb[b]) return;
    float inv = 1.f / fmaxf(g_cnt[i], 1.f);
    float* r = g_vfeat + (size_t)i * 16;
#pragma unroll
    for (int c = 0; c < 16; c++) r[c] *= inv;
}

__global__ void k_nbr() {
    int slot = blockIdx.x * blockDim.x + threadIdx.x;
    int b = blockIdx.y;
    if (slot >= g_Mb[b]) return;
    int code = g_slotcode[b * NN + slot];
    int x = code & 127, y = (code >> 7) & 127, z = code >> 14;
    const int* grid = g_grid + (size_t)b * GSIZE;
    int* dst = g_nbr + ((size_t)(b * NN + slot)) * 27;
    int ko = 0;
    for (int dz = -1; dz <= 1; dz++)
        for (int dy = -1; dy <= 1; dy++)
            for (int dx = -1; dx <= 1; dx++, ko++) {
                int nx = x + dx, ny = y + dy, nz = z + dz;
                int r = -1;
                if ((unsigned)nx < 128u && (unsigned)ny < 128u && (unsigned)nz < 128u)
                    r = grid[nx | (ny << 7) | (nz << 14)];
                dst[ko] = r;
            }
}

// ---------------- gather-GEMM conv: tile 128 voxels x COUT, f32x2 packed ----
// Layout: Xs transposed [CIN][XS] (voxel pairs contiguous -> LDS.64 broadcast),
// Ws2 holds each weight duplicated as {w,w} (LDS.64, zero packing movs).
template <int CIN, int COUT, bool BN>
__global__ void __launch_bounds__(256, 2)
conv_kernel(const float* __restrict__ fin, float* __restrict__ fout,
            const float* __restrict__ W, const float* __restrict__ bias) {
    constexpr int TV  = 128;
    constexpr int CPT = COUT / 16;   // outputs per thread (co dim)
    constexpr int HC  = CIN / 2;
    constexpr int XS  = TV + 2;      // even pad -> 8B-aligned pairs
    extern __shared__ float smem[];
    float* Ws2 = smem;                    // [CIN*COUT] float2 (dup pairs)
    float* Xs  = smem + CIN * COUT * 2;   // [CIN][XS] transposed

    int b  = blockIdx.y;
    int Mb = g_Mb[b];
    int v0 = blockIdx.x * TV;
    if (v0 >= Mb) return;

    int tid = threadIdx.x;
    int tx = tid & 15, ty = tid >> 4;

    unsigned long long acc[4][CPT];
#pragma unroll
    for (int p = 0; p < 4; p++)
#pragma unroll
        for (int j = 0; j < CPT; j++) acc[p][j] = 0ull;

    int vg = tid >> 1, half = tid & 1;
    int vidx = v0 + vg;
    bool vok = vidx < Mb;
    const int* nbrp = g_nbr + ((size_t)(b * NN + (vok ? vidx : 0))) * 27;

    for (int ko = 0; ko < 27; ko++) {
        __syncthreads();  // previous tile fully consumed
        // stage duplicated weights: Ws2[e] = {w, w}
        const float* Wk = W + ko * CIN * COUT;
        for (int e = tid; e < CIN * COUT; e += 256) {
            float w = Wk[e];
            reinterpret_cast<float2*>(Ws2)[e] = make_float2(w, w);
        }
        // gather one neighbor row (half channels per thread) into transposed Xs
        int nbr = vok ? nbrp[ko] : -1;
        if (nbr >= 0) {
            const float4* src = reinterpret_cast<const float4*>(
                fin + ((size_t)(b * NN + nbr)) * CIN) + half * (HC / 4);
#pragma unroll
            for (int q = 0; q < HC / 4; q++) {
                float4 v4 = __ldg(&src[q]);
                int c0 = half * HC + q * 4;
                if (BN) {
                    v4.x = fmaxf(fmaf(v4.x, g_scale[c0 + 0], g_shift[c0 + 0]), 0.f);
                    v4.y = fmaxf(fmaf(v4.y, g_scale[c0 + 1], g_shift[c0 + 1]), 0.f);
                    v4.z = fmaxf(fmaf(v4.z, g_scale[c0 + 2], g_shift[c0 + 2]), 0.f);
                    v4.w = fmaxf(fmaf(v4.w, g_scale[c0 + 3], g_shift[c0 + 3]), 0.f);
                }
                Xs[(c0 + 0) * XS + vg] = v4.x;
                Xs[(c0 + 1) * XS + vg] = v4.y;
                Xs[(c0 + 2) * XS + vg] = v4.z;
                Xs[(c0 + 3) * XS + vg] = v4.w;
            }
        } else {
#pragma unroll
            for (int q = 0; q < HC / 4; q++) {
                int c0 = half * HC + q * 4;
                Xs[(c0 + 0) * XS + vg] = 0.f;
                Xs[(c0 + 1) * XS + vg] = 0.f;
                Xs[(c0 + 2) * XS + vg] = 0.f;
                Xs[(c0 + 3) * XS + vg] = 0.f;
            }
        }
        __syncthreads();
#pragma unroll 4
        for (int ci = 0; ci < CIN; ci++) {
            unsigned long long xp[4];
#pragma unroll
            for (int p = 0; p < 4; p++)
                xp[p] = ld64s(&Xs[ci * XS + ty * 8 + 2 * p]);
#pragma unroll
            for (int j = 0; j < CPT; j++) {
                unsigned long long wj = ld64s(&Ws2[2 * (ci * COUT + tx + 16 * j)]);
#pragma unroll
                for (int p = 0; p < 4; p++) ffma2(acc[p][j], xp[p], wj);
            }
        }
    }
#pragma unroll
    for (int p = 0; p < 4; p++) {
        int v = v0 + ty * 8 + 2 * p;
        if (v < Mb) {
            float* dst = fout + ((size_t)(b * NN + v)) * COUT;
            bool ok1 = (v + 1) < Mb;
#pragma unroll
            for (int j = 0; j < CPT; j++) {
                float2 a = *reinterpret_cast<float2*>(&acc[p][j]);
                float bv = bias[tx + 16 * j];
                dst[tx + 16 * j] = a.x + bv;
                if (ok1) dst[COUT + tx + 16 * j] = a.y + bv;
            }
        }
    }
}

__global__ void k_zero_stats() {
    int t = threadIdx.x;
    if (t < 128) { g_sum[t] = 0.0; g_sumsq[t] = 0.0; }
}

template <int COUT>
__global__ void k_stats(const float* __restrict__ f) {
    constexpr int RP = 256 / COUT;
    int b = blockIdx.y;
    int Mb = g_Mb[b];
    int tid = threadIdx.x;
    int c = tid % COUT, r0 = tid / COUT;
    float s = 0.f, s2 = 0.f;
    for (int v = blockIdx.x * RP + r0; v < Mb; v += gridDim.x * RP) {
        float x = f[((size_t)(b * NN + v)) * COUT + c];
        s += x;
        s2 = fmaf(x, x, s2);
    }
    __shared__ float sh[256], sh2[256];
    sh[tid] = s; sh2[tid] = s2;
    __syncthreads();
    for (int st = 128; st >= COUT; st >>= 1) {
        if (tid < st) { sh[tid] += sh[tid + st]; sh2[tid] += sh2[tid + st]; }
        __syncthreads();
    }
    if (tid < COUT) {
        atomicAdd(&g_sum[tid], (double)sh[tid]);
        atomicAdd(&g_sumsq[tid], (double)sh2[tid]);
    }
}

template <int COUT>
__global__ void k_finalize(const float* __restrict__ gamma,
                           const float* __restrict__ beta) {
    int c = threadIdx.x;
    if (c >= COUT) return;
    double n = (double)g_nvalid;
    if (n < 1.0) n = 1.0;
    double mean = g_sum[c] / n;
    double var = g_sumsq[c] / n - mean * mean;
    if (var < 0.0) var = 0.0;
    float a = (float)((double)gamma[c] / sqrt(var + 1e-5));
    g_scale[c] = a;
    g_shift[c] = beta[c] - (float)mean * a;
}

__global__ void k_final(const float* __restrict__ mask, float* __restrict__ out) {
    size_t e = (size_t)blockIdx.x * blockDim.x + threadIdx.x;  // per float4
    if (e >= (size_t)NPTS * 32) return;
    int i = (int)(e >> 5);
    int c4 = (int)(e & 31);
    int b = i / NN;
    int slot = g_inv[i];
    const float4* src = reinterpret_cast<const float4*>(
        g_h3 + ((size_t)(b * NN + slot)) * 128) + c4;
    float4 h = *src;
    float m = mask[i];
    int c = c4 * 4;
    float4 y;
    y.x = fmaxf(fmaf(h.x, g_scale[c + 0], g_shift[c + 0]), 0.f) * m;
    y.y = fmaxf(fmaf(h.y, g_scale[c + 1], g_shift[c + 1]), 0.f) * m;
    y.z = fmaxf(fmaf(h.z, g_scale[c + 2], g_shift[c + 2]), 0.f) * m;
    y.w = fmaxf(fmaf(h.w, g_scale[c + 3], g_shift[c + 3]), 0.f) * m;
    reinterpret_cast<float4*>(out)[e] = y;
}

// ---------------- host ----------------
extern "C" void kernel_launch(void* const* d_in, const int* in_sizes, int n_in,
                              void* d_out, int out_size) {
    const float* xyz  = (const float*)d_in[0];
    const float* feat = (const float*)d_in[1];
    const float* mask = (const float*)d_in[2];
    const float* W1 = (const float*)d_in[3];
    const float* b1 = (const float*)d_in[4];
    const float* g1 = (const float*)d_in[5];
    const float* be1 = (const float*)d_in[6];
    const float* W2 = (const float*)d_in[7];
    const float* b2 = (const float*)d_in[8];
    const float* g2 = (const float*)d_in[9];
    const float* be2 = (const float*)d_in[10];
    const float* W3 = (const float*)d_in[11];
    const float* b3 = (const float*)d_in[12];
    const float* g3 = (const float*)d_in[13];
    const float* be3 = (const float*)d_in[14];
    float* out = (float*)d_out;

    void *pv = nullptr, *p1 = nullptr, *p2 = nullptr, *p3 = nullptr;
    cudaGetSymbolAddress(&pv, g_vfeat);
    cudaGetSymbolAddress(&p1, g_h1);
    cudaGetSymbolAddress(&p2, g_h2);
    cudaGetSymbolAddress(&p3, g_h3);

    // smem: dup weights (CIN*COUT*2) + transposed X tile (CIN*(128+2))
    size_t sm1 = (size_t)(16 * 32 * 2 + 16 * 130) * sizeof(float);   // 12.1 KB
    size_t sm2 = (size_t)(32 * 64 * 2 + 32 * 130) * sizeof(float);   // 32.3 KB
    size_t sm3 = (size_t)(64 * 128 * 2 + 64 * 130) * sizeof(float);  // 96.5 KB
    cudaFuncSetAttribute(conv_kernel<64, 128, true>,
                         cudaFuncAttributeMaxDynamicSharedMemorySize, (int)sm3);

    k_zero<<<2048, 256>>>();
    k_min<<<512, 256>>>(xyz);
    k_codes<<<NPTS / 256, 256>>>(xyz);
    k_scanA<<<4096, 1024>>>();
    k_scanB<<<8, 512>>>();
    k_sumMb<<<1, 32>>>();
    k_scanC<<<4096, 1024>>>();
    k_aggregate<<<NPTS / 256, 256>>>(feat, mask);
    k_vnorm<<<NPTS / 256, 256>>>();
    k_nbr<<<dim3(NN / 128, BB), 128>>>();

    dim3 cgrid(NN / 128, BB);

    // layer 1: vfeat(16) -> h1(32), no input affine
    conv_kernel<16, 32, false><<<cgrid, 256, sm1>>>((const float*)pv, (float*)p1, W1, b1);
    k_zero_stats<<<1, 128>>>();
    k_stats<32><<<dim3(64, BB), 256>>>((const float*)p1);
    k_finalize<32><<<1, 32>>>(g1, be1);

    // layer 2: h1(32) -> h2(64), input = relu(bn1(h1))
    conv_kernel<32, 64, true><<<cgrid, 256, sm2>>>((const float*)p1, (float*)p2, W2, b2);
    k_zero_stats<<<1, 128>>>();
    k_stats<64><<<dim3(64, BB), 256>>>((const float*)p2);
    k_finalize<64><<<1, 64>>>(g2, be2);

    // layer 3: h2(64) -> h3(128), input = relu(bn2(h2))
    conv_kernel<64, 128, true><<<cgrid, 256, sm3>>>((const float*)p2, (float*)p3, W3, b3);
    k_zero_stats<<<1, 128>>>();
    k_stats<128><<<dim3(64, BB), 256>>>((const float*)p3);
    k_finalize<128><<<1, 128>>>(g3, be3);

    // scatter: out[point] = relu(bn3(h3[inv])) * mask  (float4 vectorized)
    k_final<<<(NPTS * 32) / 256, 256>>>(mask, out);
}

// round 6
// speedup vs baseline: 2.5773x; 2.0352x over previous
#include <cuda_runtime.h>
#include <cuda_bf16.h>
#include <cstdint>

typedef unsigned short u16;

// Problem constants
#define BB    8
#define NN    65536
#define NPTS  (BB*NN)           // 524288
#define GSIZE (1<<21)           // 128^3 cells per batch
#define GTOT  (BB*GSIZE)        // 16,777,216

// ---------------- device scratch (static, no allocation) ----------------
__device__ int      g_grid[GTOT];
__device__ int      g_bsum[4096];
__device__ int      g_Mb[BB];
__device__ int      g_nvalid;
__device__ int      g_code[NPTS];
__device__ int      g_inv[NPTS];
__device__ int      g_slotcode[NPTS];
__device__ float    g_cnt[NPTS];
__device__ float    g_vfeat[(size_t)NPTS*16];
__device__ int      g_nbr[(size_t)NPTS*27];
__device__ float    g_h1[(size_t)NPTS*32];
__device__ float    g_h2[(size_t)NPTS*64];
__device__ float    g_h3[(size_t)NPTS*128];
__device__ unsigned g_obits[3];
__device__ double   g_sum[128], g_sumsq[128];
__device__ float    g_scale[128], g_shift[128];
// pre-split, pre-swizzled weights (hi/lo bf16), layout [27][COUT rows][64 u16 = 128B row]
__device__ u16      g_w1h[27*32*64],  g_w1l[27*32*64];
__device__ u16      g_w2h[27*64*64],  g_w2l[27*64*64];
__device__ u16      g_w3h[27*128*64], g_w3l[27*128*64];

// ---------------- ptx helpers (baseline PTX only: ldmatrix + mma.sync) ----
__device__ __forceinline__ uint32_t s2u(const void* p) {
    uint32_t a;
    asm("{ .reg .u64 t; cvta.to.shared.u64 t, %1; cvt.u32.u64 %0, t; }"
        : "=r"(a) : "l"(p));
    return a;
}
__device__ __forceinline__ void sts64(uint32_t addr, unsigned long long v) {
    asm volatile("st.shared.b64 [%0], %1;" :: "r"(addr), "l"(v) : "memory");
}
__device__ __forceinline__ void sts128(uint32_t addr, uint4 v) {
    asm volatile("st.shared.v4.b32 [%0], {%1,%2,%3,%4};"
                 :: "r"(addr), "r"(v.x), "r"(v.y), "r"(v.z), "r"(v.w) : "memory");
}
__device__ __forceinline__ void ldmx4(uint32_t* r, uint32_t addr) {
    asm volatile("ldmatrix.sync.aligned.m8n8.x4.shared.b16 {%0,%1,%2,%3}, [%4];"
                 : "=r"(r[0]), "=r"(r[1]), "=r"(r[2]), "=r"(r[3]) : "r"(addr));
}
__device__ __forceinline__ void ldmx2(uint32_t* r, uint32_t addr) {
    asm volatile("ldmatrix.sync.aligned.m8n8.x2.shared.b16 {%0,%1}, [%2];"
                 : "=r"(r[0]), "=r"(r[1]) : "r"(addr));
}
__device__ __forceinline__ void mma16816(float* d, const uint32_t* a,
                                         const uint32_t* b) {
    asm volatile(
        "mma.sync.aligned.m16n8k16.row.col.f32.bf16.bf16.f32 "
        "{%0,%1,%2,%3}, {%4,%5,%6,%7}, {%8,%9}, {%0,%1,%2,%3};"
        : "+f"(d[0]), "+f"(d[1]), "+f"(d[2]), "+f"(d[3])
        : "r"(a[0]), "r"(a[1]), "r"(a[2]), "r"(a[3]), "r"(b[0]), "r"(b[1]));
}
__device__ __forceinline__ uint32_t swz(uint32_t off) {
    return off ^ ((off >> 3) & 0x70);
}

// ---------------- prologue helpers ----------------
__device__ __forceinline__ int blockExclScan(int val, int &total, int nwarps) {
    int lane = threadIdx.x & 31, wid = threadIdx.x >> 5;
    int v = val;
#pragma unroll
    for (int o = 1; o < 32; o <<= 1) {
        int t = __shfl_up_sync(0xffffffffu, v, o);
        if (lane >= o) v += t;
    }
    __shared__ int ws[32];
    if (lane == 31) ws[wid] = v;
    __syncthreads();
    if (wid == 0) {
        int w = (lane < nwarps) ? ws[lane] : 0;
#pragma unroll
        for (int o = 1; o < 32; o <<= 1) {
            int t = __shfl_up_sync(0xffffffffu, w, o);
            if (lane >= o) w += t;
        }
        ws[lane] = w;
    }
    __syncthreads();
    int warpoff = wid ? ws[wid - 1] : 0;
    total = ws[nwarps - 1];
    return warpoff + v - val;
}

// ---------------- prologue kernels ----------------
__global__ void k_zero() {
    size_t i = (size_t)blockIdx.x * blockDim.x + threadIdx.x;
    size_t stride = (size_t)gridDim.x * blockDim.x;
    for (size_t j = i; j < (size_t)GTOT; j += stride) g_grid[j] = 0;
    for (size_t j = i; j < (size_t)NPTS; j += stride) g_cnt[j] = 0.f;
    for (size_t j = i; j < (size_t)NPTS * 16; j += stride) g_vfeat[j] = 0.f;
    if (i < 3) g_obits[i] = 0x7F7FFFFFu;
}

__global__ void k_min(const float* __restrict__ xyz) {
    float mn0 = 3.4e38f, mn1 = 3.4e38f, mn2 = 3.4e38f;
    for (int i = blockIdx.x * blockDim.x + threadIdx.x; i < NPTS;
         i += gridDim.x * blockDim.x) {
        mn0 = fminf(mn0, xyz[3 * i + 0]);
        mn1 = fminf(mn1, xyz[3 * i + 1]);
        mn2 = fminf(mn2, xyz[3 * i + 2]);
    }
#pragma unroll
    for (int o = 16; o; o >>= 1) {
        mn0 = fminf(mn0, __shfl_down_sync(0xffffffffu, mn0, o));
        mn1 = fminf(mn1, __shfl_down_sync(0xffffffffu, mn1, o));
        mn2 = fminf(mn2, __shfl_down_sync(0xffffffffu, mn2, o));
    }
    __shared__ float s[3][8];
    int lane = threadIdx.x & 31, wid = threadIdx.x >> 5;
    if (lane == 0) { s[0][wid] = mn0; s[1][wid] = mn1; s[2][wid] = mn2; }
    __syncthreads();
    if (threadIdx.x == 0) {
        float a = s[0][0], b = s[1][0], c = s[2][0];
        for (int w = 1; w < 8; w++) {
            a = fminf(a, s[0][w]); b = fminf(b, s[1][w]); c = fminf(c, s[2][w]);
        }
        atomicMin(&g_obits[0], __float_as_uint(a));
        atomicMin(&g_obits[1], __float_as_uint(b));
        atomicMin(&g_obits[2], __float_as_uint(c));
    }
}

__global__ void k_codes(const float* __restrict__ xyz) {
    int i = blockIdx.x * blockDim.x + threadIdx.x;
    if (i >= NPTS) return;
    int b = i / NN;
    float ox = __uint_as_float(g_obits[0]);
    float oy = __uint_as_float(g_obits[1]);
    float oz = __uint_as_float(g_obits[2]);
    int vx = (int)__fdiv_rn(xyz[3 * i + 0] - ox, 0.4f);
    int vy = (int)__fdiv_rn(xyz[3 * i + 1] - oy, 0.4f);
    int vz = (int)__fdiv_rn(xyz[3 * i + 2] - oz, 0.4f);
    vx = min(127, max(0, vx)); vy = min(127, max(0, vy)); vz = min(127, max(0, vz));
    int code = vx | (vy << 7) | (vz << 14);
    g_code[i] = code;
    g_grid[(size_t)b * GSIZE + code] = 1;
}

__global__ void k_scanA() {
    int base = blockIdx.x * 4096 + threadIdx.x * 4;
    int s = g_grid[base] + g_grid[base + 1] + g_grid[base + 2] + g_grid[base + 3];
    int tot;
    blockExclScan(s, tot, 32);
    if (threadIdx.x == 0) g_bsum[blockIdx.x] = tot;
}

__global__ void k_scanB() {
    int b = blockIdx.x, t = threadIdx.x;
    int v = g_bsum[b * 512 + t];
    int tot;
    int excl = blockExclScan(v, tot, 16);
    g_bsum[b * 512 + t] = excl;
    if (t == 511) g_Mb[b] = tot;
}

__global__ void k_sumMb() {
    if (threadIdx.x == 0) {
        int s = 0;
        for (int b = 0; b < BB; b++) s += g_Mb[b];
        g_nvalid = s;
    }
}

__global__ void k_scanC() {
    int blk = blockIdx.x;
    int b = blk >> 9;
    int cbase = (blk & 511) * 4096 + threadIdx.x * 4;
    size_t gbase = (size_t)b * GSIZE + cbase;
    int o0 = g_grid[gbase + 0], o1 = g_grid[gbase + 1];
    int o2 = g_grid[gbase + 2], o3 = g_grid[gbase + 3];
    int s = o0 + o1 + o2 + o3;
    int tot;
    int excl = blockExclScan(s, tot, 32);
    int run = g_bsum[blk] + excl;
    int occ[4] = {o0, o1, o2, o3};
#pragma unroll
    for (int j = 0; j < 4; j++) {
        if (occ[j]) {
            g_grid[gbase + j] = run;
            g_slotcode[b * NN + run] = cbase + j;
            run++;
        } else {
            g_grid[gbase + j] = -1;
        }
    }
}

__global__ void k_aggregate(const float* __restrict__ feat,
                            const float* __restrict__ mask) {
    int i = blockIdx.x * blockDim.x + threadIdx.x;
    if (i >= NPTS) return;
    int b = i / NN;
    int code = g_code[i];
    int slot = g_grid[(size_t)b * GSIZE + code];
    g_inv[i] = slot;
    float m = mask[i];
    if (m != 0.f) {
        int row = b * NN + slot;
        atomicAdd(&g_cnt[row], m);
        const float* f = feat + (size_t)i * 16;
        float* dst = g_vfeat + (size_t)row * 16;
#pragma unroll
        for (int c = 0; c < 16; c++) atomicAdd(&dst[c], f[c] * m);
    }
}

__global__ void k_vnorm() {
    int i = blockIdx.x * blockDim.x + threadIdx.x;
    if (i >= NPTS) return;
    int b = i / NN, slot = i - b * NN;
    if (slot >= g_Mb[b]) return;
    float inv = 1.f / fmaxf(g_cnt[i], 1.f);
    float* r = g_vfeat + (size_t)i * 16;
#pragma unroll
    for (int c = 0; c < 16; c++) r[c] *= inv;
}

__global__ void k_nbr() {
    int slot = blockIdx.x * blockDim.x + threadIdx.x;
    int b = blockIdx.y;
    if (slot >= g_Mb[b]) return;
    int code = g_slotcode[b * NN + slot];
    int x = code & 127, y = (code >> 7) & 127, z = code >> 14;
    const int* grid = g_grid + (size_t)b * GSIZE;
    int* dst = g_nbr + ((size_t)(b * NN + slot)) * 27;
    int ko = 0;
    for (int dz = -1; dz <= 1; dz++)
        for (int dy = -1; dy <= 1; dy++)
            for (int dx = -1; dx <= 1; dx++, ko++) {
                int nx = x + dx, ny = y + dy, nz = z + dz;
                int r = -1;
                if ((unsigned)nx < 128u && (unsigned)ny < 128u && (unsigned)nz < 128u)
                    r = grid[nx | (ny << 7) | (nz << 14)];
                dst[ko] = r;
            }
}

// ---------------- weight pre-split (hi/lo bf16, swizzled layout) --------
template <int CIN, int COUT>
__global__ void k_wsplit(const float* __restrict__ W,
                         u16* __restrict__ Wh, u16* __restrict__ Wl) {
    int i = blockIdx.x * blockDim.x + threadIdx.x;
    if (i >= 27 * COUT * 64) return;
    int cil = i & 63;              // logical u16 column (ci)
    int co = (i >> 6) % COUT;      // row = output channel
    int ko = i / (64 * COUT);
    float w = (cil < CIN) ? W[(ko * CIN + cil) * COUT + co] : 0.f;
    __nv_bfloat16 h = __float2bfloat16(w);
    float rem = w - __bfloat162float(h);
    __nv_bfloat16 l = __float2bfloat16(rem);
    uint32_t off = co * 128 + cil * 2;
    uint32_t sw = swz(off);
    size_t base = (size_t)ko * COUT * 64;
    Wh[base + sw / 2] = *reinterpret_cast<u16*>(&h);
    Wl[base + sw / 2] = *reinterpret_cast<u16*>(&l);
}

// ---------------- warp-MMA split-bf16 gather-conv -------------------------
// 128-voxel tile per CTA (8 warps x 16 voxels). D kept in registers; per tap:
// stage W(hi/lo) + gather A(hi/lo, BN+ReLU) into SW128 smem, then ldmatrix +
// mma.sync m16n8k16 (3 split combos, xl*wl dropped).
template <int CIN, int COUT, bool BN>
__global__ void __launch_bounds__(256, 2)
conv_wmma(const float* __restrict__ fin, float* __restrict__ fout,
          const u16* __restrict__ Wh, const u16* __restrict__ Wl,
          const float* __restrict__ bias) {
    constexpr int HC = CIN / 2;
    constexpr int CK = CIN / 16;      // k-chunks of 16
    constexpr int NT = COUT / 8;      // n-tiles of 8
    constexpr int ABYTES = 128 * 128;
    constexpr int BBYTES = COUT * 128;
    extern __shared__ char smem[];

    int b = blockIdx.y;
    int Mb = g_Mb[b];
    int v0 = blockIdx.x * 128;
    if (v0 >= Mb) return;
    int tid = threadIdx.x, wid = tid >> 5, lane = tid & 31;

    uint32_t sbase = s2u(smem);
    uint32_t abase = (sbase + 1023) & ~1023u;
    uint32_t Ah = abase, Al = abase + ABYTES;
    uint32_t Bh = abase + 2 * ABYTES, Bl = Bh + BBYTES;

    // gather setup: thread pair per voxel row, half channels each
    int vg = tid >> 1, half = tid & 1;
    int vidx = v0 + vg;
    bool vok = vidx < Mb;
    const int* nbrp = g_nbr + ((size_t)(b * NN + (vok ? vidx : 0))) * 27;
    uint32_t rowoff = vg * 128 + half * (HC * 2);

    // ldmatrix lane address bases
    uint32_t a_off0 = (uint32_t)(wid * 16 + (lane & 15)) * 128 + (lane >> 4) * 16;
    uint32_t b_row = lane & 7;
    uint32_t b_kh = (lane >> 3) & 1;

    float d[NT][4];
#pragma unroll
    for (int nt = 0; nt < NT; nt++)
#pragma unroll
        for (int j = 0; j < 4; j++) d[nt][j] = 0.f;

    for (int ko = 0; ko < 27; ko++) {
        if (ko) __syncthreads();   // all warps done with previous tap's tiles
        // stage B (pre-swizzled in gmem -> straight uint4 copy)
        {
            const uint4* sh = (const uint4*)(Wh + (size_t)ko * (COUT * 64));
            const uint4* sl = (const uint4*)(Wl + (size_t)ko * (COUT * 64));
#pragma unroll
            for (int e = tid; e < BBYTES / 16; e += 256) {
                sts128(Bh + e * 16, __ldg(&sh[e]));
                sts128(Bl + e * 16, __ldg(&sl[e]));
            }
        }
        // gather A rows, BN+ReLU, hi/lo split, swizzled store
        int nbr = vok ? nbrp[ko] : -1;
        if (nbr >= 0) {
            const float4* src = (const float4*)(fin + ((size_t)(b * NN + nbr)) * CIN)
                                + half * (HC / 4);
#pragma unroll
            for (int q = 0; q < HC / 4; q++) {
                float4 x = __ldg(&src[q]);
                int c0 = half * HC + 4 * q;
                if (BN) {
                    x.x = fmaxf(fmaf(x.x, g_scale[c0 + 0], g_shift[c0 + 0]), 0.f);
                    x.y = fmaxf(fmaf(x.y, g_scale[c0 + 1], g_shift[c0 + 1]), 0.f);
                    x.z = fmaxf(fmaf(x.z, g_scale[c0 + 2], g_shift[c0 + 2]), 0.f);
                    x.w = fmaxf(fmaf(x.w, g_scale[c0 + 3], g_shift[c0 + 3]), 0.f);
                }
                __nv_bfloat162 h0 = __float22bfloat162_rn(make_float2(x.x, x.y));
                __nv_bfloat162 h1 = __float22bfloat162_rn(make_float2(x.z, x.w));
                float2 r0 = make_float2(x.x - __bfloat162float(h0.x),
                                        x.y - __bfloat162float(h0.y));
                float2 r1 = make_float2(x.z - __bfloat162float(h1.x),
                                        x.w - __bfloat162float(h1.y));
                __nv_bfloat162 l0 = __float22bfloat162_rn(r0);
                __nv_bfloat162 l1 = __float22bfloat162_rn(r1);
                unsigned long long hp =
                    (unsigned long long)(*reinterpret_cast<uint32_t*>(&h0)) |
                    ((unsigned long long)(*reinterpret_cast<uint32_t*>(&h1)) << 32);
                unsigned long long lp =
                    (unsigned long long)(*reinterpret_cast<uint32_t*>(&l0)) |
                    ((unsigned long long)(*reinterpret_cast<uint32_t*>(&l1)) << 32);
                uint32_t sw = swz(rowoff + 8 * q);
                sts64(Ah + sw, hp);
                sts64(Al + sw, lp);
            }
        } else {
#pragma unroll
            for (int q = 0; q < HC / 4; q++) {
                uint32_t sw = swz(rowoff + 8 * q);
                sts64(Ah + sw, 0ull);
                sts64(Al + sw, 0ull);
            }
        }
        __syncthreads();
        // compute: ldmatrix + 3x mma.sync per (kc, nt)
#pragma unroll
        for (int kc = 0; kc < CK; kc++) {
            uint32_t asw = swz(a_off0 + kc * 32);
            uint32_t ah[4], al[4];
            ldmx4(ah, Ah + asw);
            ldmx4(al, Al + asw);
#pragma unroll
            for (int nt = 0; nt < NT; nt++) {
                uint32_t boff = (nt * 8 + b_row) * 128 + kc * 32 + b_kh * 16;
                uint32_t bsw = swz(boff);
                uint32_t bh[2], bl[2];
                ldmx2(bh, Bh + bsw);
                ldmx2(bl, Bl + bsw);
                mma16816(d[nt], ah, bh);
                mma16816(d[nt], ah, bl);
                mma16816(d[nt], al, bh);
            }
        }
    }
    // epilogue: D regs -> gmem (+bias). Thread t: rows m0, m0+8; cols 2 per nt.
    int m0 = v0 + wid * 16 + (lane >> 2);
    int col0 = (lane & 3) * 2;
    bool ok0 = m0 < Mb, ok1 = (m0 + 8) < Mb;
    float* dst0 = fout + ((size_t)(b * NN + m0)) * COUT;
    float* dst1 = dst0 + (size_t)8 * COUT;
#pragma unroll
    for (int nt = 0; nt < NT; nt++) {
        int c = nt * 8 + col0;
        float bx = bias[c], by = bias[c + 1];
        if (ok0)
            *reinterpret_cast<float2*>(dst0 + c) =
                make_float2(d[nt][0] + bx, d[nt][1] + by);
        if (ok1)
            *reinterpret_cast<float2*>(dst1 + c) =
                make_float2(d[nt][2] + bx, d[nt][3] + by);
    }
}

// ---------------- BN stats / finalize / output ---------------------------
__global__ void k_zero_stats() {
    int t = threadIdx.x;
    if (t < 128) { g_sum[t] = 0.0; g_sumsq[t] = 0.0; }
}

template <int COUT>
__global__ void k_stats(const float* __restrict__ f) {
    constexpr int RP = 256 / COUT;
    int b = blockIdx.y;
    int Mb = g_Mb[b];
    int tid = threadIdx.x;
    int c = tid % COUT, r0 = tid / COUT;
    float s = 0.f, s2 = 0.f;
    for (int v = blockIdx.x * RP + r0; v < Mb; v += gridDim.x * RP) {
        float x = f[((size_t)(b * NN + v)) * COUT + c];
        s += x;
        s2 = fmaf(x, x, s2);
    }
    __shared__ float sh[256], sh2[256];
    sh[tid] = s; sh2[tid] = s2;
    __syncthreads();
    for (int st = 128; st >= COUT; st >>= 1) {
        if (tid < st) { sh[tid] += sh[tid + st]; sh2[tid] += sh2[tid + st]; }
        __syncthreads();
    }
    if (tid < COUT) {
        atomicAdd(&g_sum[tid], (double)sh[tid]);
        atomicAdd(&g_sumsq[tid], (double)sh2[tid]);
    }
}

template <int COUT>
__global__ void k_finalize(const float* __restrict__ gamma,
                           const float* __restrict__ beta) {
    int c = threadIdx.x;
    if (c >= COUT) return;
    double n = (double)g_nvalid;
    if (n < 1.0) n = 1.0;
    double mean = g_sum[c] / n;
    double var = g_sumsq[c] / n - mean * mean;
    if (var < 0.0) var = 0.0;
    float a = (float)((double)gamma[c] / sqrt(var + 1e-5));
    g_scale[c] = a;
    g_shift[c] = beta[c] - (float)mean * a;
}

__global__ void k_final(const float* __restrict__ mask, float* __restrict__ out) {
    size_t e = (size_t)blockIdx.x * blockDim.x + threadIdx.x;  // per float4
    if (e >= (size_t)NPTS * 32) return;
    int i = (int)(e >> 5);
    int c4 = (int)(e & 31);
    int b = i / NN;
    int slot = g_inv[i];
    const float4* src = reinterpret_cast<const float4*>(
        g_h3 + ((size_t)(b * NN + slot)) * 128) + c4;
    float4 h = *src;
    float m = mask[i];
    int c = c4 * 4;
    float4 y;
    y.x = fmaxf(fmaf(h.x, g_scale[c + 0], g_shift[c + 0]), 0.f) * m;
    y.y = fmaxf(fmaf(h.y, g_scale[c + 1], g_shift[c + 1]), 0.f) * m;
    y.z = fmaxf(fmaf(h.z, g_scale[c + 2], g_shift[c + 2]), 0.f) * m;
    y.w = fmaxf(fmaf(h.w, g_scale[c + 3], g_shift[c + 3]), 0.f) * m;
    reinterpret_cast<float4*>(out)[e] = y;
}

// ---------------- host ----------------
extern "C" void kernel_launch(void* const* d_in, const int* in_sizes, int n_in,
                              void* d_out, int out_size) {
    const float* xyz  = (const float*)d_in[0];
    const float* feat = (const float*)d_in[1];
    const float* mask = (const float*)d_in[2];
    const float* W1 = (const float*)d_in[3];
    const float* b1 = (const float*)d_in[4];
    const float* g1 = (const float*)d_in[5];
    const float* be1 = (const float*)d_in[6];
    const float* W2 = (const float*)d_in[7];
    const float* b2 = (const float*)d_in[8];
    const float* g2 = (const float*)d_in[9];
    const float* be2 = (const float*)d_in[10];
    const float* W3 = (const float*)d_in[11];
    const float* b3 = (const float*)d_in[12];
    const float* g3 = (const float*)d_in[13];
    const float* be3 = (const float*)d_in[14];
    float* out = (float*)d_out;

    void *pv, *p1, *p2, *p3;
    void *w1h, *w1l, *w2h, *w2l, *w3h, *w3l;
    cudaGetSymbolAddress(&pv, g_vfeat);
    cudaGetSymbolAddress(&p1, g_h1);
    cudaGetSymbolAddress(&p2, g_h2);
    cudaGetSymbolAddress(&p3, g_h3);
    cudaGetSymbolAddress(&w1h, g_w1h); cudaGetSymbolAddress(&w1l, g_w1l);
    cudaGetSymbolAddress(&w2h, g_w2h); cudaGetSymbolAddress(&w2l, g_w2l);
    cudaGetSymbolAddress(&w3h, g_w3h); cudaGetSymbolAddress(&w3l, g_w3l);

    // dynamic smem: 1024 align slack + 2*A(16KB) + 2*B(COUT*128)
    int sm1 = 1024 + 2 * 16384 + 2 * (32 * 128);    // 41984
    int sm2 = 1024 + 2 * 16384 + 2 * (64 * 128);    // 50176
    int sm3 = 1024 + 2 * 16384 + 2 * (128 * 128);   // 66560
    cudaFuncSetAttribute(conv_wmma<16, 32, false>,
                         cudaFuncAttributeMaxDynamicSharedMemorySize, sm1);
    cudaFuncSetAttribute(conv_wmma<32, 64, true>,
                         cudaFuncAttributeMaxDynamicSharedMemorySize, sm2);
    cudaFuncSetAttribute(conv_wmma<64, 128, true>,
                         cudaFuncAttributeMaxDynamicSharedMemorySize, sm3);

    k_zero<<<2048, 256>>>();
    k_wsplit<16, 32><<<(27 * 32 * 64 + 255) / 256, 256>>>(W1, (u16*)w1h, (u16*)w1l);
    k_wsplit<32, 64><<<(27 * 64 * 64 + 255) / 256, 256>>>(W2, (u16*)w2h, (u16*)w2l);
    k_wsplit<64, 128><<<(27 * 128 * 64 + 255) / 256, 256>>>(W3, (u16*)w3h, (u16*)w3l);
    k_min<<<512, 256>>>(xyz);
    k_codes<<<NPTS / 256, 256>>>(xyz);
    k_scanA<<<4096, 1024>>>();
    k_scanB<<<8, 512>>>();
    k_sumMb<<<1, 32>>>();
    k_scanC<<<4096, 1024>>>();
    k_aggregate<<<NPTS / 256, 256>>>(feat, mask);
    k_vnorm<<<NPTS / 256, 256>>>();
    k_nbr<<<dim3(NN / 128, BB), 128>>>();

    dim3 cgrid(NN / 128, BB);

    // layer 1: vfeat(16) -> h1(32)
    conv_wmma<16, 32, false><<<cgrid, 256, sm1>>>((const float*)pv, (float*)p1,
                                                  (const u16*)w1h, (const u16*)w1l, b1);
    k_zero_stats<<<1, 128>>>();
    k_stats<32><<<dim3(64, BB), 256>>>((const float*)p1);
    k_finalize<32><<<1, 32>>>(g1, be1);

    // layer 2: h1(32) -> h2(64), input = relu(bn1(h1))
    conv_wmma<32, 64, true><<<cgrid, 256, sm2>>>((const float*)p1, (float*)p2,
                                                 (const u16*)w2h, (const u16*)w2l, b2);
    k_zero_stats<<<1, 128>>>();
    k_stats<64><<<dim3(64, BB), 256>>>((const float*)p2);
    k_finalize<64><<<1, 64>>>(g2, be2);

    // layer 3: h2(64) -> h3(128), input = relu(bn2(h2))
    conv_wmma<64, 128, true><<<cgrid, 256, sm3>>>((const float*)p2, (float*)p3,
                                                  (const u16*)w3h, (const u16*)w3l, b3);
    k_zero_stats<<<1, 128>>>();
    k_stats<128><<<dim3(64, BB), 256>>>((const float*)p3);
    k_finalize<128><<<1, 128>>>(g3, be3);

    // scatter: out[point] = relu(bn3(h3[inv])) * mask
    k_final<<<(NPTS * 32) / 256, 256>>>(mask, out);
}

// round 7
// speedup vs baseline: 3.2662x; 1.2673x over previous
#include <cuda_runtime.h>
#include <cuda_bf16.h>
#include <cstdint>

typedef unsigned short u16;
typedef unsigned long long u64;

// Problem constants
#define BB    8
#define NN    65536
#define NPTS  (BB*NN)           // 524288
#define GSIZE (1<<21)           // 128^3 cells per batch
#define GTOT  (BB*GSIZE)        // 16,777,216

// ---------------- device scratch (static, no allocation) ----------------
__device__ int      g_grid[GTOT];
__device__ int      g_bsum[4096];
__device__ int      g_Mb[BB];
__device__ int      g_nvalid;
__device__ int      g_code[NPTS];
__device__ int      g_inv[NPTS];
__device__ int      g_slotcode[NPTS];
__device__ float    g_cnt[NPTS];
__device__ float    g_vfeat[(size_t)NPTS*16];
__device__ int      g_nbr[(size_t)NPTS*27];
__device__ float    g_h1[(size_t)NPTS*32];
__device__ float    g_h2[(size_t)NPTS*64];
__device__ float    g_h3[(size_t)NPTS*128];
__device__ unsigned g_obits[3];
__device__ double   g_sum[128], g_sumsq[128];
__device__ float    g_scale[128], g_shift[128];
// pre-split hi/lo bf16 inputs per layer: voxel row = [hi CIN u16][lo CIN u16]
__device__ u16      g_x1[(size_t)NPTS*32];
__device__ u16      g_x2[(size_t)NPTS*64];
__device__ u16      g_x3[(size_t)NPTS*128];
// pre-split, pre-swizzled weight tiles (smem images)
__device__ u16      g_w1[27*32*64];    // hi cols 0-15, lo cols 16-31
__device__ u16      g_w2[27*64*64];    // hi cols 0-31, lo cols 32-63
__device__ u16      g_w3[27*128*128];  // hi subtile 16KB then lo subtile 16KB

// ---------------- ptx helpers ----------------
__device__ __forceinline__ uint32_t s2u(const void* p) {
    uint32_t a;
    asm("{ .reg .u64 t; cvta.to.shared.u64 t, %1; cvt.u32.u64 %0, t; }"
        : "=r"(a) : "l"(p));
    return a;
}
__device__ __forceinline__ void cpasync16(uint32_t dst, const void* src, uint32_t sz) {
    asm volatile("cp.async.cg.shared.global [%0], [%1], 16, %2;"
                 :: "r"(dst), "l"(src), "r"(sz) : "memory");
}
__device__ __forceinline__ void cpcommit() {
    asm volatile("cp.async.commit_group;" ::: "memory");
}
template <int N>
__device__ __forceinline__ void cpwait() {
    asm volatile("cp.async.wait_group %0;" :: "n"(N) : "memory");
}
__device__ __forceinline__ void ldmx4(uint32_t* r, uint32_t addr) {
    asm volatile("ldmatrix.sync.aligned.m8n8.x4.shared.b16 {%0,%1,%2,%3}, [%4];"
                 : "=r"(r[0]), "=r"(r[1]), "=r"(r[2]), "=r"(r[3]) : "r"(addr));
}
__device__ __forceinline__ void mma16816(float* d, const uint32_t* a,
                                         const uint32_t* b) {
    asm volatile(
        "mma.sync.aligned.m16n8k16.row.col.f32.bf16.bf16.f32 "
        "{%0,%1,%2,%3}, {%4,%5,%6,%7}, {%8,%9}, {%0,%1,%2,%3};"
        : "+f"(d[0]), "+f"(d[1]), "+f"(d[2]), "+f"(d[3])
        : "r"(a[0]), "r"(a[1]), "r"(a[2]), "r"(a[3]), "r"(b[0]), "r"(b[1]));
}
__device__ __forceinline__ uint32_t swz(uint32_t off) {
    return off ^ ((off >> 3) & 0x70);
}

// ---------------- prologue helpers ----------------
__device__ __forceinline__ int blockExclScan(int val, int &total, int nwarps) {
    int lane = threadIdx.x & 31, wid = threadIdx.x >> 5;
    int v = val;
#pragma unroll
    for (int o = 1; o < 32; o <<= 1) {
        int t = __shfl_up_sync(0xffffffffu, v, o);
        if (lane >= o) v += t;
    }
    __shared__ int ws[32];
    if (lane == 31) ws[wid] = v;
    __syncthreads();
    if (wid == 0) {
        int w = (lane < nwarps) ? ws[lane] : 0;
#pragma unroll
        for (int o = 1; o < 32; o <<= 1) {
            int t = __shfl_up_sync(0xffffffffu, w, o);
            if (lane >= o) w += t;
        }
        ws[lane] = w;
    }
    __syncthreads();
    int warpoff = wid ? ws[wid - 1] : 0;
    total = ws[nwarps - 1];
    return warpoff + v - val;
}

// ---------------- prologue kernels ----------------
__global__ void k_zero() {
    size_t i = (size_t)blockIdx.x * blockDim.x + threadIdx.x;
    size_t stride = (size_t)gridDim.x * blockDim.x;
    for (size_t j = i; j < (size_t)GTOT; j += stride) g_grid[j] = 0;
    for (size_t j = i; j < (size_t)NPTS; j += stride) g_cnt[j] = 0.f;
    for (size_t j = i; j < (size_t)NPTS * 16; j += stride) g_vfeat[j] = 0.f;
    if (i < 3) g_obits[i] = 0x7F7FFFFFu;
}

__global__ void k_min(const float* __restrict__ xyz) {
    float mn0 = 3.4e38f, mn1 = 3.4e38f, mn2 = 3.4e38f;
    for (int i = blockIdx.x * blockDim.x + threadIdx.x; i < NPTS;
         i += gridDim.x * blockDim.x) {
        mn0 = fminf(mn0, xyz[3 * i + 0]);
        mn1 = fminf(mn1, xyz[3 * i + 1]);
        mn2 = fminf(mn2, xyz[3 * i + 2]);
    }
#pragma unroll
    for (int o = 16; o; o >>= 1) {
        mn0 = fminf(mn0, __shfl_down_sync(0xffffffffu, mn0, o));
        mn1 = fminf(mn1, __shfl_down_sync(0xffffffffu, mn1, o));
        mn2 = fminf(mn2, __shfl_down_sync(0xffffffffu, mn2, o));
    }
    __shared__ float s[3][8];
    int lane = threadIdx.x & 31, wid = threadIdx.x >> 5;
    if (lane == 0) { s[0][wid] = mn0; s[1][wid] = mn1; s[2][wid] = mn2; }
    __syncthreads();
    if (threadIdx.x == 0) {
        float a = s[0][0], b = s[1][0], c = s[2][0];
        for (int w = 1; w < 8; w++) {
            a = fminf(a, s[0][w]); b = fminf(b, s[1][w]); c = fminf(c, s[2][w]);
        }
        atomicMin(&g_obits[0], __float_as_uint(a));
        atomicMin(&g_obits[1], __float_as_uint(b));
        atomicMin(&g_obits[2], __float_as_uint(c));
    }
}

__global__ void k_codes(const float* __restrict__ xyz) {
    int i = blockIdx.x * blockDim.x + threadIdx.x;
    if (i >= NPTS) return;
    int b = i / NN;
    float ox = __uint_as_float(g_obits[0]);
    float oy = __uint_as_float(g_obits[1]);
    float oz = __uint_as_float(g_obits[2]);
    int vx = (int)__fdiv_rn(xyz[3 * i + 0] - ox, 0.4f);
    int vy = (int)__fdiv_rn(xyz[3 * i + 1] - oy, 0.4f);
    int vz = (int)__fdiv_rn(xyz[3 * i + 2] - oz, 0.4f);
    vx = min(127, max(0, vx)); vy = min(127, max(0, vy)); vz = min(127, max(0, vz));
    int code = vx | (vy << 7) | (vz << 14);
    g_code[i] = code;
    g_grid[(size_t)b * GSIZE + code] = 1;
}

__global__ void k_scanA() {
    int base = blockIdx.x * 4096 + threadIdx.x * 4;
    int s = g_grid[base] + g_grid[base + 1] + g_grid[base + 2] + g_grid[base + 3];
    int tot;
    blockExclScan(s, tot, 32);
    if (threadIdx.x == 0) g_bsum[blockIdx.x] = tot;
}

__global__ void k_scanB() {
    int b = blockIdx.x, t = threadIdx.x;
    int v = g_bsum[b * 512 + t];
    int tot;
    int excl = blockExclScan(v, tot, 16);
    g_bsum[b * 512 + t] = excl;
    if (t == 511) g_Mb[b] = tot;
}

__global__ void k_sumMb() {
    if (threadIdx.x == 0) {
        int s = 0;
        for (int b = 0; b < BB; b++) s += g_Mb[b];
        g_nvalid = s;
    }
}

__global__ void k_scanC() {
    int blk = blockIdx.x;
    int b = blk >> 9;
    int cbase = (blk & 511) * 4096 + threadIdx.x * 4;
    size_t gbase = (size_t)b * GSIZE + cbase;
    int o0 = g_grid[gbase + 0], o1 = g_grid[gbase + 1];
    int o2 = g_grid[gbase + 2], o3 = g_grid[gbase + 3];
    int s = o0 + o1 + o2 + o3;
    int tot;
    int excl = blockExclScan(s, tot, 32);
    int run = g_bsum[blk] + excl;
    int occ[4] = {o0, o1, o2, o3};
#pragma unroll
    for (int j = 0; j < 4; j++) {
        if (occ[j]) {
            g_grid[gbase + j] = run;
            g_slotcode[b * NN + run] = cbase + j;
            run++;
        } else {
            g_grid[gbase + j] = -1;
        }
    }
}

__global__ void k_aggregate(const float* __restrict__ feat,
                            const float* __restrict__ mask) {
    int i = blockIdx.x * blockDim.x + threadIdx.x;
    if (i >= NPTS) return;
    int b = i / NN;
    int code = g_code[i];
    int slot = g_grid[(size_t)b * GSIZE + code];
    g_inv[i] = slot;
    float m = mask[i];
    if (m != 0.f) {
        int row = b * NN + slot;
        atomicAdd(&g_cnt[row], m);
        const float* f = feat + (size_t)i * 16;
        float* dst = g_vfeat + (size_t)row * 16;
#pragma unroll
        for (int c = 0; c < 16; c++) atomicAdd(&dst[c], f[c] * m);
    }
}

// normalize voxel features and emit split bf16 hi/lo rows for conv1
__global__ void k_vnorm() {
    int i = blockIdx.x * blockDim.x + threadIdx.x;
    if (i >= NPTS) return;
    int b = i / NN, slot = i - b * NN;
    if (slot >= g_Mb[b]) return;
    float inv = 1.f / fmaxf(g_cnt[i], 1.f);
    const float* r = g_vfeat + (size_t)i * 16;
    u16* dst = g_x1 + (size_t)i * 32;
#pragma unroll
    for (int q = 0; q < 4; q++) {
        float4 x = *reinterpret_cast<const float4*>(r + 4 * q);
        x.x *= inv; x.y *= inv; x.z *= inv; x.w *= inv;
        __nv_bfloat162 h0 = __float22bfloat162_rn(make_float2(x.x, x.y));
        __nv_bfloat162 h1 = __float22bfloat162_rn(make_float2(x.z, x.w));
        __nv_bfloat162 l0 = __float22bfloat162_rn(
            make_float2(x.x - __bfloat162float(h0.x), x.y - __bfloat162float(h0.y)));
        __nv_bfloat162 l1 = __float22bfloat162_rn(
            make_float2(x.z - __bfloat162float(h1.x), x.w - __bfloat162float(h1.y)));
        *reinterpret_cast<u64*>(dst + 4 * q) =
            (u64)(*reinterpret_cast<uint32_t*>(&h0)) |
            ((u64)(*reinterpret_cast<uint32_t*>(&h1)) << 32);
        *reinterpret_cast<u64*>(dst + 16 + 4 * q) =
            (u64)(*reinterpret_cast<uint32_t*>(&l0)) |
            ((u64)(*reinterpret_cast<uint32_t*>(&l1)) << 32);
    }
}

__global__ void k_nbr() {
    int slot = blockIdx.x * blockDim.x + threadIdx.x;
    int b = blockIdx.y;
    if (slot >= g_Mb[b]) return;
    int code = g_slotcode[b * NN + slot];
    int x = code & 127, y = (code >> 7) & 127, z = code >> 14;
    const int* grid = g_grid + (size_t)b * GSIZE;
    int* dst = g_nbr + ((size_t)(b * NN + slot)) * 27;
    int ko = 0;
    for (int dz = -1; dz <= 1; dz++)
        for (int dy = -1; dy <= 1; dy++)
            for (int dx = -1; dx <= 1; dx++, ko++) {
                int nx = x + dx, ny = y + dy, nz = z + dz;
                int r = -1;
                if ((unsigned)nx < 128u && (unsigned)ny < 128u && (unsigned)nz < 128u)
                    r = grid[nx | (ny << 7) | (nz << 14)];
                dst[ko] = r;
            }
}

// ---------------- weight pre-split into swizzled smem-image tiles --------
template <int CIN, int COUT>
__global__ void k_wsplit(const float* __restrict__ W, u16* __restrict__ Wout) {
    constexpr bool SPLIT = (CIN == 64);
    constexpr int TILE_U16 = COUT * 64 * (SPLIT ? 2 : 1);
    int i = blockIdx.x * blockDim.x + threadIdx.x;
    if (i >= 27 * COUT * CIN) return;
    int cil = i % CIN;
    int co = (i / CIN) % COUT;
    int ko = i / (CIN * COUT);
    float w = W[(ko * CIN + cil) * COUT + co];
    __nv_bfloat16 h = __float2bfloat16(w);
    float rem = w - __bfloat162float(h);
    __nv_bfloat16 l = __float2bfloat16(rem);
    size_t base = (size_t)ko * TILE_U16;
    uint32_t hoff = swz((uint32_t)(co * 128 + cil * 2));
    Wout[base + hoff / 2] = *reinterpret_cast<u16*>(&h);
    if (SPLIT) {
        Wout[base + COUT * 64 + hoff / 2] = *reinterpret_cast<u16*>(&l);
    } else {
        uint32_t loff = swz((uint32_t)(co * 128 + (CIN + cil) * 2));
        Wout[base + loff / 2] = *reinterpret_cast<u16*>(&l);
    }
}

// ---------------- BN+ReLU + hi/lo split of a feature map ----------------
template <int C>
__global__ void k_split(const float* __restrict__ in, u16* __restrict__ out) {
    int idx = blockIdx.x * blockDim.x + threadIdx.x;
    if (idx >= NPTS * (C / 4)) return;
    int v = idx / (C / 4);
    int q = idx - v * (C / 4);
    int c0 = 4 * q;
    float4 x = reinterpret_cast<const float4*>(in)[idx];
    x.x = fmaxf(fmaf(x.x, g_scale[c0 + 0], g_shift[c0 + 0]), 0.f);
    x.y = fmaxf(fmaf(x.y, g_scale[c0 + 1], g_shift[c0 + 1]), 0.f);
    x.z = fmaxf(fmaf(x.z, g_scale[c0 + 2], g_shift[c0 + 2]), 0.f);
    x.w = fmaxf(fmaf(x.w, g_scale[c0 + 3], g_shift[c0 + 3]), 0.f);
    __nv_bfloat162 h0 = __float22bfloat162_rn(make_float2(x.x, x.y));
    __nv_bfloat162 h1 = __float22bfloat162_rn(make_float2(x.z, x.w));
    __nv_bfloat162 l0 = __float22bfloat162_rn(
        make_float2(x.x - __bfloat162float(h0.x), x.y - __bfloat162float(h0.y)));
    __nv_bfloat162 l1 = __float22bfloat162_rn(
        make_float2(x.z - __bfloat162float(h1.x), x.w - __bfloat162float(h1.y)));
    u16* row = out + (size_t)v * 2 * C;
    *reinterpret_cast<u64*>(row + c0) =
        (u64)(*reinterpret_cast<uint32_t*>(&h0)) |
        ((u64)(*reinterpret_cast<uint32_t*>(&h1)) << 32);
    *reinterpret_cast<u64*>(row + C + c0) =
        (u64)(*reinterpret_cast<uint32_t*>(&l0)) |
        ((u64)(*reinterpret_cast<uint32_t*>(&l1)) << 32);
}

// ---------------- cp.async-pipelined warp-MMA gather-conv -----------------
// 128-voxel tile per CTA, batch-major 1D grid. 3-deep pipeline: stage tap
// ko+1 (A rows via cp.async from pre-split bf16 features; B = verbatim copy
// of pre-swizzled weight tile) while computing tap ko with ldmatrix+mma.sync.
template <int CIN, int COUT>
__global__ void __launch_bounds__(256, (CIN == 64) ? 1 : 2)
conv_pipe(const u16* __restrict__ X, float* __restrict__ fout,
          const u16* __restrict__ Wg, const float* __restrict__ bias) {
    constexpr int CK = CIN / 16;
    constexpr int NT = COUT / 8;
    constexpr int NP = NT / 2;
    constexpr bool SPLIT = (CIN == 64);
    constexpr int ATILE = SPLIT ? 32768 : 16384;
    constexpr int BTILE = COUT * 128 * (SPLIT ? 2 : 1);
    constexpr int BUFSZ = ATILE + BTILE;
    constexpr int RB = 4 * CIN;          // gmem bytes per voxel row (hi+lo)
    constexpr int CPT = RB / 32;         // 16B chunks per thread (2 thr/row)
    constexpr uint32_t LO = SPLIT ? 16384u : (uint32_t)(CIN * 2);
    extern __shared__ char smem[];

    int blk = blockIdx.x;
    int b = blk >> 9, tilei = blk & 511;
    int Mb = g_Mb[b];
    int v0 = tilei * 128;
    if (v0 >= Mb) return;
    int tid = threadIdx.x, wid = tid >> 5, lane = tid & 31;

    uint32_t sbase = (s2u(smem) + 1023) & ~1023u;

    int vg = tid >> 1, half = tid & 1;
    bool vok = (v0 + vg) < Mb;
    const int* nbrp = g_nbr + ((size_t)(b * NN + (vok ? v0 + vg : 0))) * 27;
    uint32_t arow = (uint32_t)vg * 128;

    uint32_t a_off0 = (uint32_t)(wid * 16 + (lane & 15)) * 128 + (lane >> 4) * 16;
    uint32_t b_off0 = (uint32_t)((lane >> 4) * 8 + (lane & 7)) * 128 +
                      ((lane >> 3) & 1) * 16;

    float d[NT][4];
#pragma unroll
    for (int nt = 0; nt < NT; nt++)
#pragma unroll
        for (int j = 0; j < 4; j++) d[nt][j] = 0.f;

    const u16* Xb = X + (size_t)b * NN * (RB / 2);

    auto stage = [&](int ko, int buf, int nbr) {
        uint32_t sB = sbase + buf * BUFSZ + ATILE;
        const char* wsrc = (const char*)Wg + (size_t)ko * BTILE;
#pragma unroll
        for (int e = 0; e < BTILE / 16 / 256; e++) {
            int idx = tid + e * 256;
            cpasync16(sB + idx * 16, wsrc + idx * 16, 16);
        }
        uint32_t sA = sbase + buf * BUFSZ;
        uint32_t sz = (nbr >= 0) ? 16u : 0u;
        const char* xs = (const char*)(Xb + (size_t)max(nbr, 0) * (RB / 2));
#pragma unroll
        for (int j2 = 0; j2 < CPT; j2++) {
            int j = half * CPT + j2;
            uint32_t doff = SPLIT
                ? ((uint32_t)(j & 7) * 16 + (uint32_t)(j >> 3) * 16384u)
                : (uint32_t)j * 16;
            cpasync16(sA + swz(arow + doff), xs + j * 16, sz);
        }
    };

    auto compute = [&](int buf) {
        uint32_t sA = sbase + buf * BUFSZ;
        uint32_t sB = sA + ATILE;
#pragma unroll
        for (int kc = 0; kc < CK; kc++) {
            uint32_t ah[4], al[4];
            ldmx4(ah, sA + swz(a_off0 + kc * 32));
            ldmx4(al, sA + swz(a_off0 + kc * 32 + LO));
#pragma unroll
            for (int p = 0; p < NP; p++) {
                uint32_t bh[4], bl[4];
                ldmx4(bh, sB + swz(b_off0 + p * 2048 + kc * 32));
                ldmx4(bl, sB + swz(b_off0 + p * 2048 + kc * 32 + LO));
                mma16816(d[2 * p],     ah, bh);
                mma16816(d[2 * p + 1], ah, bh + 2);
                mma16816(d[2 * p],     ah, bl);
                mma16816(d[2 * p + 1], ah, bl + 2);
                mma16816(d[2 * p],     al, bh);
                mma16816(d[2 * p + 1], al, bh + 2);
            }
        }
    };

    int nbr_c = vok ? __ldg(&nbrp[0]) : -1;
    stage(0, 0, nbr_c);
    cpcommit();
    int nbr_n = vok ? __ldg(&nbrp[1]) : -1;
    for (int ko = 0; ko < 27; ko++) {
        int nxt = ko + 1;
        if (nxt < 27) {
            stage(nxt, nxt % 3, nbr_n);
            cpcommit();
            nbr_n = (vok && nxt + 1 < 27) ? __ldg(&nbrp[nxt + 1]) : -1;
            cpwait<1>();
        } else {
            cpwait<0>();
        }
        __syncthreads();
        compute(ko % 3);
    }

    // epilogue: D regs -> gmem (+bias)
    int m0 = v0 + wid * 16 + (lane >> 2);
    int col0 = (lane & 3) * 2;
    bool ok0 = m0 < Mb, ok1 = (m0 + 8) < Mb;
    float* dst0 = fout + ((size_t)(b * NN + m0)) * COUT;
    float* dst1 = dst0 + (size_t)8 * COUT;
#pragma unroll
    for (int nt = 0; nt < NT; nt++) {
        int c = nt * 8 + col0;
        float bx = bias[c], by = bias[c + 1];
        if (ok0)
            *reinterpret_cast<float2*>(dst0 + c) =
                make_float2(d[nt][0] + bx, d[nt][1] + by);
        if (ok1)
            *reinterpret_cast<float2*>(dst1 + c) =
                make_float2(d[nt][2] + bx, d[nt][3] + by);
    }
}

// ---------------- BN stats / finalize / output ---------------------------
__global__ void k_zero_stats() {
    int t = threadIdx.x;
    if (t < 128) { g_sum[t] = 0.0; g_sumsq[t] = 0.0; }
}

template <int COUT>
__global__ void k_stats(const float* __restrict__ f) {
    constexpr int RP = 256 / COUT;
    int b = blockIdx.y;
    int Mb = g_Mb[b];
    int tid = threadIdx.x;
    int c = tid % COUT, r0 = tid / COUT;
    float s = 0.f, s2 = 0.f;
    for (int v = blockIdx.x * RP + r0; v < Mb; v += gridDim.x * RP) {
        float x = f[((size_t)(b * NN + v)) * COUT + c];
        s += x;
        s2 = fmaf(x, x, s2);
    }
    __shared__ float sh[256], sh2[256];
    sh[tid] = s; sh2[tid] = s2;
    __syncthreads();
    for (int st = 128; st >= COUT; st >>= 1) {
        if (tid < st) { sh[tid] += sh[tid + st]; sh2[tid] += sh2[tid + st]; }
        __syncthreads();
    }
    if (tid < COUT) {
        atomicAdd(&g_sum[tid], (double)sh[tid]);
        atomicAdd(&g_sumsq[tid], (double)sh2[tid]);
    }
}

template <int COUT>
__global__ void k_finalize(const float* __restrict__ gamma,
                           const float* __restrict__ beta) {
    int c = threadIdx.x;
    if (c >= COUT) return;
    double n = (double)g_nvalid;
    if (n < 1.0) n = 1.0;
    double mean = g_sum[c] / n;
    double var = g_sumsq[c] / n - mean * mean;
    if (var < 0.0) var = 0.0;
    float a = (float)((double)gamma[c] / sqrt(var + 1e-5));
    g_scale[c] = a;
    g_shift[c] = beta[c] - (float)mean * a;
}

__global__ void k_final(const float* __restrict__ mask, float* __restrict__ out) {
    size_t e = (size_t)blockIdx.x * blockDim.x + threadIdx.x;  // per float4
    if (e >= (size_t)NPTS * 32) return;
    int i = (int)(e >> 5);
    int c4 = (int)(e & 31);
    int b = i / NN;
    int slot = g_inv[i];
    const float4* src = reinterpret_cast<const float4*>(
        g_h3 + ((size_t)(b * NN + slot)) * 128) + c4;
    float4 h = *src;
    float m = mask[i];
    int c = c4 * 4;
    float4 y;
    y.x = fmaxf(fmaf(h.x, g_scale[c + 0], g_shift[c + 0]), 0.f) * m;
    y.y = fmaxf(fmaf(h.y, g_scale[c + 1], g_shift[c + 1]), 0.f) * m;
    y.z = fmaxf(fmaf(h.z, g_scale[c + 2], g_shift[c + 2]), 0.f) * m;
    y.w = fmaxf(fmaf(h.w, g_scale[c + 3], g_shift[c + 3]), 0.f) * m;
    reinterpret_cast<float4*>(out)[e] = y;
}

// ---------------- host ----------------
extern "C" void kernel_launch(void* const* d_in, const int* in_sizes, int n_in,
                              void* d_out, int out_size) {
    const float* xyz  = (const float*)d_in[0];
    const float* feat = (const float*)d_in[1];
    const float* mask = (const float*)d_in[2];
    const float* W1 = (const float*)d_in[3];
    const float* b1 = (const float*)d_in[4];
    const float* g1 = (const float*)d_in[5];
    const float* be1 = (const float*)d_in[6];
    const float* W2 = (const float*)d_in[7];
    const float* b2 = (const float*)d_in[8];
    const float* g2 = (const float*)d_in[9];
    const float* be2 = (const float*)d_in[10];
    const float* W3 = (const float*)d_in[11];
    const float* b3 = (const float*)d_in[12];
    const float* g3 = (const float*)d_in[13];
    const float* be3 = (const float*)d_in[14];
    float* out = (float*)d_out;

    void *p1, *p2, *p3, *x1, *x2, *x3, *w1, *w2, *w3;
    cudaGetSymbolAddress(&p1, g_h1);
    cudaGetSymbolAddress(&p2, g_h2);
    cudaGetSymbolAddress(&p3, g_h3);
    cudaGetSymbolAddress(&x1, g_x1);
    cudaGetSymbolAddress(&x2, g_x2);
    cudaGetSymbolAddress(&x3, g_x3);
    cudaGetSymbolAddress(&w1, g_w1);
    cudaGetSymbolAddress(&w2, g_w2);
    cudaGetSymbolAddress(&w3, g_w3);

    // dynamic smem: 1KB align slack + 3 pipeline buffers
    int sm1 = 1024 + 3 * (16384 + 32 * 128);        // 62464
    int sm2 = 1024 + 3 * (16384 + 64 * 128);        // 74752
    int sm3 = 1024 + 3 * (32768 + 128 * 128 * 2);   // 197632
    cudaFuncSetAttribute(conv_pipe<16, 32>,
                         cudaFuncAttributeMaxDynamicSharedMemorySize, sm1);
    cudaFuncSetAttribute(conv_pipe<32, 64>,
                         cudaFuncAttributeMaxDynamicSharedMemorySize, sm2);
    cudaFuncSetAttribute(conv_pipe<64, 128>,
                         cudaFuncAttributeMaxDynamicSharedMemorySize, sm3);

    k_zero<<<2048, 256>>>();
    k_wsplit<16, 32><<<(27 * 32 * 16 + 255) / 256, 256>>>(W1, (u16*)w1);
    k_wsplit<32, 64><<<(27 * 64 * 32 + 255) / 256, 256>>>(W2, (u16*)w2);
    k_wsplit<64, 128><<<(27 * 128 * 64 + 255) / 256, 256>>>(W3, (u16*)w3);
    k_min<<<512, 256>>>(xyz);
    k_codes<<<NPTS / 256, 256>>>(xyz);
    k_scanA<<<4096, 1024>>>();
    k_scanB<<<8, 512>>>();
    k_sumMb<<<1, 32>>>();
    k_scanC<<<4096, 1024>>>();
    k_aggregate<<<NPTS / 256, 256>>>(feat, mask);
    k_vnorm<<<NPTS / 256, 256>>>();
    k_nbr<<<dim3(NN / 128, BB), 128>>>();

    // layer 1: x1(16, split) -> h1(32)
    conv_pipe<16, 32><<<BB * 512, 256, sm1>>>((const u16*)x1, (float*)p1,
                                              (const u16*)w1, b1);
    k_zero_stats<<<1, 128>>>();
    k_stats<32><<<dim3(64, BB), 256>>>((const float*)p1);
    k_finalize<32><<<1, 32>>>(g1, be1);
    k_split<32><<<(NPTS * 8 + 255) / 256, 256>>>((const float*)p1, (u16*)x2);

    // layer 2: x2(32, split) -> h2(64)
    conv_pipe<32, 64><<<BB * 512, 256, sm2>>>((const u16*)x2, (float*)p2,
                                              (const u16*)w2, b2);
    k_zero_stats<<<1, 128>>>();
    k_stats<64><<<dim3(64, BB), 256>>>((const float*)p2);
    k_finalize<64><<<1, 64>>>(g2, be2);
    k_split<64><<<(NPTS * 16 + 255) / 256, 256>>>((const float*)p2, (u16*)x3);

    // layer 3: x3(64, split) -> h3(128)
    conv_pipe<64, 128><<<BB * 512, 256, sm3>>>((const u16*)x3, (float*)p3,
                                               (const u16*)w3, b3);
    k_zero_stats<<<1, 128>>>();
    k_stats<128><<<dim3(64, BB), 256>>>((const float*)p3);
    k_finalize<128><<<1, 128>>>(g3, be3);

    // scatter: out[point] = relu(bn3(h3[inv])) * mask
    k_final<<<(NPTS * 32 + 255) / 256, 256>>>(mask, out);
}

// round 8
// speedup vs baseline: 3.5309x; 1.0810x over previous
#include <cuda_runtime.h>
#include <cuda_bf16.h>
#include <cstdint>

typedef unsigned short u16;
typedef unsigned long long u64;

// Problem constants
#define BB    8
#define NN    65536
#define NPTS  (BB*NN)           // 524288
#define GSIZE (1<<21)           // 128^3 cells per batch
#define GTOT  (BB*GSIZE)        // 16,777,216

// ---------------- device scratch (static, no allocation) ----------------
__device__ int      g_grid[GTOT];
__device__ int      g_bsum[4096];
__device__ int      g_Mb[BB];
__device__ int      g_nvalid;
__device__ int      g_code[NPTS];
__device__ int      g_inv[NPTS];
__device__ int      g_slotcode[NPTS];
__device__ float    g_cnt[NPTS];
__device__ float    g_vfeat[(size_t)NPTS*16];
__device__ int      g_nbr[(size_t)NPTS*27];   // TRANSPOSED: [ko][b*NN+slot]
__device__ float    g_h1[(size_t)NPTS*32];
__device__ float    g_h2[(size_t)NPTS*64];
__device__ float    g_h3[(size_t)NPTS*128];
__device__ unsigned g_obits[3];
__device__ double   g_sum[128], g_sumsq[128];
__device__ float    g_scale[128], g_shift[128];
// pre-split hi/lo bf16 inputs per layer: voxel row = [hi CIN u16][lo CIN u16]
__device__ u16      g_x1[(size_t)NPTS*32];
__device__ u16      g_x2[(size_t)NPTS*64];
__device__ u16      g_x3[(size_t)NPTS*128];
// pre-split, pre-swizzled weight tiles (smem images)
__device__ u16      g_w1[27*32*64];    // hi cols 0-15, lo cols 16-31
__device__ u16      g_w2[27*64*64];    // hi cols 0-31, lo cols 32-63
__device__ u16      g_w3[27*128*128];  // hi subtile 16KB then lo subtile 16KB

// ---------------- ptx helpers ----------------
__device__ __forceinline__ uint32_t s2u(const void* p) {
    uint32_t a;
    asm("{ .reg .u64 t; cvta.to.shared.u64 t, %1; cvt.u32.u64 %0, t; }"
        : "=r"(a) : "l"(p));
    return a;
}
__device__ __forceinline__ void cpasync16(uint32_t dst, const void* src, uint32_t sz) {
    asm volatile("cp.async.cg.shared.global [%0], [%1], 16, %2;"
                 :: "r"(dst), "l"(src), "r"(sz) : "memory");
}
__device__ __forceinline__ void cpcommit() {
    asm volatile("cp.async.commit_group;" ::: "memory");
}
template <int N>
__device__ __forceinline__ void cpwait() {
    asm volatile("cp.async.wait_group %0;" :: "n"(N) : "memory");
}
__device__ __forceinline__ void ldmx4(uint32_t* r, uint32_t addr) {
    asm volatile("ldmatrix.sync.aligned.m8n8.x4.shared.b16 {%0,%1,%2,%3}, [%4];"
                 : "=r"(r[0]), "=r"(r[1]), "=r"(r[2]), "=r"(r[3]) : "r"(addr));
}
__device__ __forceinline__ void mma16816(float* d, const uint32_t* a,
                                         const uint32_t* b) {
    asm volatile(
        "mma.sync.aligned.m16n8k16.row.col.f32.bf16.bf16.f32 "
        "{%0,%1,%2,%3}, {%4,%5,%6,%7}, {%8,%9}, {%0,%1,%2,%3};"
        : "+f"(d[0]), "+f"(d[1]), "+f"(d[2]), "+f"(d[3])
        : "r"(a[0]), "r"(a[1]), "r"(a[2]), "r"(a[3]), "r"(b[0]), "r"(b[1]));
}
__device__ __forceinline__ uint32_t swz(uint32_t off) {
    return off ^ ((off >> 3) & 0x70);
}

// ---------------- prologue helpers ----------------
__device__ __forceinline__ int blockExclScan(int val, int &total, int nwarps) {
    int lane = threadIdx.x & 31, wid = threadIdx.x >> 5;
    int v = val;
#pragma unroll
    for (int o = 1; o < 32; o <<= 1) {
        int t = __shfl_up_sync(0xffffffffu, v, o);
        if (lane >= o) v += t;
    }
    __shared__ int ws[32];
    if (lane == 31) ws[wid] = v;
    __syncthreads();
    if (wid == 0) {
        int w = (lane < nwarps) ? ws[lane] : 0;
#pragma unroll
        for (int o = 1; o < 32; o <<= 1) {
            int t = __shfl_up_sync(0xffffffffu, w, o);
            if (lane >= o) w += t;
        }
        ws[lane] = w;
    }
    __syncthreads();
    int warpoff = wid ? ws[wid - 1] : 0;
    total = ws[nwarps - 1];
    return warpoff + v - val;
}

// ---------------- prologue kernels ----------------
__global__ void k_zero() {
    size_t i = (size_t)blockIdx.x * blockDim.x + threadIdx.x;
    size_t stride = (size_t)gridDim.x * blockDim.x;
    for (size_t j = i; j < (size_t)GTOT; j += stride) g_grid[j] = 0;
    for (size_t j = i; j < (size_t)NPTS; j += stride) g_cnt[j] = 0.f;
    for (size_t j = i; j < (size_t)NPTS * 16; j += stride) g_vfeat[j] = 0.f;
    if (i < 3) g_obits[i] = 0x7F7FFFFFu;
}

__global__ void k_min(const float* __restrict__ xyz) {
    float mn0 = 3.4e38f, mn1 = 3.4e38f, mn2 = 3.4e38f;
    for (int i = blockIdx.x * blockDim.x + threadIdx.x; i < NPTS;
         i += gridDim.x * blockDim.x) {
        mn0 = fminf(mn0, xyz[3 * i + 0]);
        mn1 = fminf(mn1, xyz[3 * i + 1]);
        mn2 = fminf(mn2, xyz[3 * i + 2]);
    }
#pragma unroll
    for (int o = 16; o; o >>= 1) {
        mn0 = fminf(mn0, __shfl_down_sync(0xffffffffu, mn0, o));
        mn1 = fminf(mn1, __shfl_down_sync(0xffffffffu, mn1, o));
        mn2 = fminf(mn2, __shfl_down_sync(0xffffffffu, mn2, o));
    }
    __shared__ float s[3][8];
    int lane = threadIdx.x & 31, wid = threadIdx.x >> 5;
    if (lane == 0) { s[0][wid] = mn0; s[1][wid] = mn1; s[2][wid] = mn2; }
    __syncthreads();
    if (threadIdx.x == 0) {
        float a = s[0][0], b = s[1][0], c = s[2][0];
        for (int w = 1; w < 8; w++) {
            a = fminf(a, s[0][w]); b = fminf(b, s[1][w]); c = fminf(c, s[2][w]);
        }
        atomicMin(&g_obits[0], __float_as_uint(a));
        atomicMin(&g_obits[1], __float_as_uint(b));
        atomicMin(&g_obits[2], __float_as_uint(c));
    }
}

__global__ void k_codes(const float* __restrict__ xyz) {
    int i = blockIdx.x * blockDim.x + threadIdx.x;
    if (i >= NPTS) return;
    int b = i / NN;
    float ox = __uint_as_float(g_obits[0]);
    float oy = __uint_as_float(g_obits[1]);
    float oz = __uint_as_float(g_obits[2]);
    int vx = (int)__fdiv_rn(xyz[3 * i + 0] - ox, 0.4f);
    int vy = (int)__fdiv_rn(xyz[3 * i + 1] - oy, 0.4f);
    int vz = (int)__fdiv_rn(xyz[3 * i + 2] - oz, 0.4f);
    vx = min(127, max(0, vx)); vy = min(127, max(0, vy)); vz = min(127, max(0, vz));
    int code = vx | (vy << 7) | (vz << 14);
    g_code[i] = code;
    g_grid[(size_t)b * GSIZE + code] = 1;
}

__global__ void k_scanA() {
    int base = blockIdx.x * 4096 + threadIdx.x * 4;
    int s = g_grid[base] + g_grid[base + 1] + g_grid[base + 2] + g_grid[base + 3];
    int tot;
    blockExclScan(s, tot, 32);
    if (threadIdx.x == 0) g_bsum[blockIdx.x] = tot;
}

__global__ void k_scanB() {
    int b = blockIdx.x, t = threadIdx.x;
    int v = g_bsum[b * 512 + t];
    int tot;
    int excl = blockExclScan(v, tot, 16);
    g_bsum[b * 512 + t] = excl;
    if (t == 511) g_Mb[b] = tot;
}

__global__ void k_sumMb() {
    if (threadIdx.x == 0) {
        int s = 0;
        for (int b = 0; b < BB; b++) s += g_Mb[b];
        g_nvalid = s;
    }
}

__global__ void k_scanC() {
    int blk = blockIdx.x;
    int b = blk >> 9;
    int cbase = (blk & 511) * 4096 + threadIdx.x * 4;
    size_t gbase = (size_t)b * GSIZE + cbase;
    int o0 = g_grid[gbase + 0], o1 = g_grid[gbase + 1];
    int o2 = g_grid[gbase + 2], o3 = g_grid[gbase + 3];
    int s = o0 + o1 + o2 + o3;
    int tot;
    int excl = blockExclScan(s, tot, 32);
    int run = g_bsum[blk] + excl;
    int occ[4] = {o0, o1, o2, o3};
#pragma unroll
    for (int j = 0; j < 4; j++) {
        if (occ[j]) {
            g_grid[gbase + j] = run;
            g_slotcode[b * NN + run] = cbase + j;
            run++;
        } else {
            g_grid[gbase + j] = -1;
        }
    }
}

__global__ void k_aggregate(const float* __restrict__ feat,
                            const float* __restrict__ mask) {
    int i = blockIdx.x * blockDim.x + threadIdx.x;
    if (i >= NPTS) return;
    int b = i / NN;
    int code = g_code[i];
    int slot = g_grid[(size_t)b * GSIZE + code];
    g_inv[i] = slot;
    float m = mask[i];
    if (m != 0.f) {
        int row = b * NN + slot;
        atomicAdd(&g_cnt[row], m);
        const float* f = feat + (size_t)i * 16;
        float* dst = g_vfeat + (size_t)row * 16;
#pragma unroll
        for (int c = 0; c < 16; c++) atomicAdd(&dst[c], f[c] * m);
    }
}

// normalize voxel features and emit split bf16 hi/lo rows for conv1
__global__ void k_vnorm() {
    int i = blockIdx.x * blockDim.x + threadIdx.x;
    if (i >= NPTS) return;
    int b = i / NN, slot = i - b * NN;
    if (slot >= g_Mb[b]) return;
    float inv = 1.f / fmaxf(g_cnt[i], 1.f);
    const float* r = g_vfeat + (size_t)i * 16;
    u16* dst = g_x1 + (size_t)i * 32;
#pragma unroll
    for (int q = 0; q < 4; q++) {
        float4 x = *reinterpret_cast<const float4*>(r + 4 * q);
        x.x *= inv; x.y *= inv; x.z *= inv; x.w *= inv;
        __nv_bfloat162 h0 = __float22bfloat162_rn(make_float2(x.x, x.y));
        __nv_bfloat162 h1 = __float22bfloat162_rn(make_float2(x.z, x.w));
        __nv_bfloat162 l0 = __float22bfloat162_rn(
            make_float2(x.x - __bfloat162float(h0.x), x.y - __bfloat162float(h0.y)));
        __nv_bfloat162 l1 = __float22bfloat162_rn(
            make_float2(x.z - __bfloat162float(h1.x), x.w - __bfloat162float(h1.y)));
        *reinterpret_cast<u64*>(dst + 4 * q) =
            (u64)(*reinterpret_cast<uint32_t*>(&h0)) |
            ((u64)(*reinterpret_cast<uint32_t*>(&h1)) << 32);
        *reinterpret_cast<u64*>(dst + 16 + 4 * q) =
            (u64)(*reinterpret_cast<uint32_t*>(&l0)) |
            ((u64)(*reinterpret_cast<uint32_t*>(&l1)) << 32);
    }
}

__global__ void k_nbr() {
    int slot = blockIdx.x * blockDim.x + threadIdx.x;
    int b = blockIdx.y;
    if (slot >= g_Mb[b]) return;
    int code = g_slotcode[b * NN + slot];
    int x = code & 127, y = (code >> 7) & 127, z = code >> 14;
    const int* grid = g_grid + (size_t)b * GSIZE;
    int row = b * NN + slot;
    int ko = 0;
    for (int dz = -1; dz <= 1; dz++)
        for (int dy = -1; dy <= 1; dy++)
            for (int dx = -1; dx <= 1; dx++, ko++) {
                int nx = x + dx, ny = y + dy, nz = z + dz;
                int r = -1;
                if ((unsigned)nx < 128u && (unsigned)ny < 128u && (unsigned)nz < 128u)
                    r = grid[nx | (ny << 7) | (nz << 14)];
                g_nbr[(size_t)ko * NPTS + row] = r;   // transposed layout
            }
}

// ---------------- weight pre-split into swizzled smem-image tiles --------
template <int CIN, int COUT>
__global__ void k_wsplit(const float* __restrict__ W, u16* __restrict__ Wout) {
    constexpr bool SPLIT = (CIN == 64);
    constexpr int TILE_U16 = COUT * 64 * (SPLIT ? 2 : 1);
    int i = blockIdx.x * blockDim.x + threadIdx.x;
    if (i >= 27 * COUT * CIN) return;
    int cil = i % CIN;
    int co = (i / CIN) % COUT;
    int ko = i / (CIN * COUT);
    float w = W[(ko * CIN + cil) * COUT + co];
    __nv_bfloat16 h = __float2bfloat16(w);
    float rem = w - __bfloat162float(h);
    __nv_bfloat16 l = __float2bfloat16(rem);
    size_t base = (size_t)ko * TILE_U16;
    uint32_t hoff = swz((uint32_t)(co * 128 + cil * 2));
    Wout[base + hoff / 2] = *reinterpret_cast<u16*>(&h);
    if (SPLIT) {
        Wout[base + COUT * 64 + hoff / 2] = *reinterpret_cast<u16*>(&l);
    } else {
        uint32_t loff = swz((uint32_t)(co * 128 + (CIN + cil) * 2));
        Wout[base + loff / 2] = *reinterpret_cast<u16*>(&l);
    }
}

// ---------------- BN+ReLU + hi/lo split of a feature map ----------------
template <int C>
__global__ void k_split(const float* __restrict__ in, u16* __restrict__ out) {
    int idx = blockIdx.x * blockDim.x + threadIdx.x;
    if (idx >= NPTS * (C / 4)) return;
    int v = idx / (C / 4);
    int q = idx - v * (C / 4);
    int c0 = 4 * q;
    float4 x = reinterpret_cast<const float4*>(in)[idx];
    x.x = fmaxf(fmaf(x.x, g_scale[c0 + 0], g_shift[c0 + 0]), 0.f);
    x.y = fmaxf(fmaf(x.y, g_scale[c0 + 1], g_shift[c0 + 1]), 0.f);
    x.z = fmaxf(fmaf(x.z, g_scale[c0 + 2], g_shift[c0 + 2]), 0.f);
    x.w = fmaxf(fmaf(x.w, g_scale[c0 + 3], g_shift[c0 + 3]), 0.f);
    __nv_bfloat162 h0 = __float22bfloat162_rn(make_float2(x.x, x.y));
    __nv_bfloat162 h1 = __float22bfloat162_rn(make_float2(x.z, x.w));
    __nv_bfloat162 l0 = __float22bfloat162_rn(
        make_float2(x.x - __bfloat162float(h0.x), x.y - __bfloat162float(h0.y)));
    __nv_bfloat162 l1 = __float22bfloat162_rn(
        make_float2(x.z - __bfloat162float(h1.x), x.w - __bfloat162float(h1.y)));
    u16* row = out + (size_t)v * 2 * C;
    *reinterpret_cast<u64*>(row + c0) =
        (u64)(*reinterpret_cast<uint32_t*>(&h0)) |
        ((u64)(*reinterpret_cast<uint32_t*>(&h1)) << 32);
    *reinterpret_cast<u64*>(row + C + c0) =
        (u64)(*reinterpret_cast<uint32_t*>(&l0)) |
        ((u64)(*reinterpret_cast<uint32_t*>(&l1)) << 32);
}

// ---------------- cp.async-pipelined warp-MMA gather-conv, M=256 ----------
// 256-voxel tile per CTA; 8 warps each own 32 rows x full COUT. 2-deep
// cp.async pipeline (stage tap ko+1 while computing ko), 2 barriers/tap.
template <int CIN, int COUT>
__global__ void __launch_bounds__(256, (CIN == 64) ? 1 : 2)
conv_pipe(const u16* __restrict__ X, float* __restrict__ fout,
          const u16* __restrict__ Wg, const float* __restrict__ bias) {
    constexpr int CK = CIN / 16;
    constexpr int NT = COUT / 8;
    constexpr int NP = NT / 2;
    constexpr bool SPLIT = (CIN == 64);
    constexpr int ATILE = SPLIT ? 65536 : 32768;   // 256 rows x 128B (+lo subtile)
    constexpr int BTILE = COUT * 128 * (SPLIT ? 2 : 1);
    constexpr int BUFSZ = ATILE + BTILE;
    constexpr int RB = 4 * CIN;          // gmem bytes per voxel row (hi+lo)
    constexpr int CPT = RB / 16;         // 16B chunks per row (1 thread/row)
    constexpr uint32_t LOA = SPLIT ? 32768u : (uint32_t)(CIN * 2);
    constexpr uint32_t LOB = SPLIT ? 16384u : (uint32_t)(CIN * 2);
    extern __shared__ char smem[];

    int blk = blockIdx.x;
    int b = blk >> 8, tilei = blk & 255;
    int Mb = g_Mb[b];
    int v0 = tilei * 256;
    if (v0 >= Mb) return;
    int tid = threadIdx.x, wid = tid >> 5, lane = tid & 31;

    uint32_t sbase = (s2u(smem) + 1023) & ~1023u;

    // staging: one thread per voxel row
    int gv = b * NN + v0 + tid;
    bool vok = (v0 + tid) < Mb;
    uint32_t arow = (uint32_t)tid * 128;

    // ldmatrix lane bases
    uint32_t a_off0 = (uint32_t)(wid * 32 + (lane & 15)) * 128 + (lane >> 4) * 16;
    uint32_t b_off0 = (uint32_t)((lane >> 4) * 8 + (lane & 7)) * 128 +
                      ((lane >> 3) & 1) * 16;

    float d[2][NT][4];
#pragma unroll
    for (int mt = 0; mt < 2; mt++)
#pragma unroll
        for (int nt = 0; nt < NT; nt++)
#pragma unroll
            for (int j = 0; j < 4; j++) d[mt][nt][j] = 0.f;

    const u16* Xb = X + (size_t)b * NN * (RB / 2);

    auto stage = [&](int ko, int buf, int nbr) {
        uint32_t sB = sbase + buf * BUFSZ + ATILE;
        const char* wsrc = (const char*)Wg + (size_t)ko * BTILE;
#pragma unroll
        for (int e = 0; e < BTILE / 16 / 256; e++) {
            int idx = tid + e * 256;
            cpasync16(sB + idx * 16, wsrc + idx * 16, 16);
        }
        uint32_t sA = sbase + buf * BUFSZ;
        uint32_t sz = (nbr >= 0) ? 16u : 0u;
        const char* xs = (const char*)(Xb + (size_t)max(nbr, 0) * (RB / 2));
#pragma unroll
        for (int j = 0; j < CPT; j++) {
            uint32_t doff = SPLIT
                ? (((j >= 8) ? 32768u : 0u) + swz(arow + (j & 7) * 16))
                : swz(arow + (uint32_t)j * 16);
            cpasync16(sA + doff, xs + j * 16, sz);
        }
    };

    auto compute = [&](int buf) {
        uint32_t sA = sbase + buf * BUFSZ;
        uint32_t sB = sA + ATILE;
#pragma unroll
        for (int kc = 0; kc < CK; kc++) {
            uint32_t ah[2][4], al[2][4];
#pragma unroll
            for (int mt = 0; mt < 2; mt++) {
                uint32_t ao = a_off0 + (uint32_t)mt * 16 * 128 + kc * 32;
                ldmx4(ah[mt], sA + swz(ao));
                ldmx4(al[mt], sA + swz(ao + LOA));
            }
#pragma unroll
            for (int p = 0; p < NP; p++) {
                uint32_t bh[4], bl[4];
                uint32_t bo = b_off0 + p * 2048 + kc * 32;
                ldmx4(bh, sB + swz(bo));
                ldmx4(bl, sB + swz(bo + LOB));
#pragma unroll
                for (int mt = 0; mt < 2; mt++) {
                    mma16816(d[mt][2 * p],     ah[mt], bh);
                    mma16816(d[mt][2 * p + 1], ah[mt], bh + 2);
                    mma16816(d[mt][2 * p],     ah[mt], bl);
                    mma16816(d[mt][2 * p + 1], ah[mt], bl + 2);
                    mma16816(d[mt][2 * p],     al[mt], bh);
                    mma16816(d[mt][2 * p + 1], al[mt], bh + 2);
                }
            }
        }
    };

    int nbr_c = vok ? __ldg(&g_nbr[gv]) : -1;               // tap 0
    stage(0, 0, nbr_c);
    cpcommit();
    int nbr_n = vok ? __ldg(&g_nbr[(size_t)NPTS + gv]) : -1; // tap 1
    for (int ko = 0; ko < 27; ko++) {
        int nxt = ko + 1;
        if (nxt < 27) {
            stage(nxt, nxt & 1, nbr_n);
            cpcommit();
            nbr_n = (vok && nxt + 1 < 27)
                ? __ldg(&g_nbr[(size_t)(nxt + 1) * NPTS + gv]) : -1;
            cpwait<1>();
        } else {
            cpwait<0>();
        }
        __syncthreads();
        compute(ko & 1);
        __syncthreads();   // buffer (ko&1) free for restage at iter ko+1
    }

    // epilogue: D regs -> gmem (+bias)
    int col0 = (lane & 3) * 2;
#pragma unroll
    for (int mt = 0; mt < 2; mt++) {
        int m0 = v0 + wid * 32 + mt * 16 + (lane >> 2);
        bool ok0 = m0 < Mb, ok1 = (m0 + 8) < Mb;
        float* dst0 = fout + ((size_t)(b * NN + m0)) * COUT;
        float* dst1 = dst0 + (size_t)8 * COUT;
#pragma unroll
        for (int nt = 0; nt < NT; nt++) {
            int c = nt * 8 + col0;
            float bx = bias[c], by = bias[c + 1];
            if (ok0)
                *reinterpret_cast<float2*>(dst0 + c) =
                    make_float2(d[mt][nt][0] + bx, d[mt][nt][1] + by);
            if (ok1)
                *reinterpret_cast<float2*>(dst1 + c) =
                    make_float2(d[mt][nt][2] + bx, d[mt][nt][3] + by);
        }
    }
}

// ---------------- BN stats / finalize / output ---------------------------
__global__ void k_zero_stats() {
    int t = threadIdx.x;
    if (t < 128) { g_sum[t] = 0.0; g_sumsq[t] = 0.0; }
}

template <int COUT>
__global__ void k_stats(const float* __restrict__ f) {
    constexpr int RP = 256 / COUT;
    int b = blockIdx.y;
    int Mb = g_Mb[b];
    int tid = threadIdx.x;
    int c = tid % COUT, r0 = tid / COUT;
    float s = 0.f, s2 = 0.f;
    for (int v = blockIdx.x * RP + r0; v < Mb; v += gridDim.x * RP) {
        float x = f[((size_t)(b * NN + v)) * COUT + c];
        s += x;
        s2 = fmaf(x, x, s2);
    }
    __shared__ float sh[256], sh2[256];
    sh[tid] = s; sh2[tid] = s2;
    __syncthreads();
    for (int st = 128; st >= COUT; st >>= 1) {
        if (tid < st) { sh[tid] += sh[tid + st]; sh2[tid] += sh2[tid + st]; }
        __syncthreads();
    }
    if (tid < COUT) {
        atomicAdd(&g_sum[tid], (double)sh[tid]);
        atomicAdd(&g_sumsq[tid], (double)sh2[tid]);
    }
}

template <int COUT>
__global__ void k_finalize(const float* __restrict__ gamma,
                           const float* __restrict__ beta) {
    int c = threadIdx.x;
    if (c >= COUT) return;
    double n = (double)g_nvalid;
    if (n < 1.0) n = 1.0;
    double mean = g_sum[c] / n;
    double var = g_sumsq[c] / n - mean * mean;
    if (var < 0.0) var = 0.0;
    float a = (float)((double)gamma[c] / sqrt(var + 1e-5));
    g_scale[c] = a;
    g_shift[c] = beta[c] - (float)mean * a;
}

__global__ void k_final(const float* __restrict__ mask, float* __restrict__ out) {
    size_t e = (size_t)blockIdx.x * blockDim.x + threadIdx.x;  // per float4
    if (e >= (size_t)NPTS * 32) return;
    int i = (int)(e >> 5);
    int c4 = (int)(e & 31);
    int b = i / NN;
    int slot = g_inv[i];
    const float4* src = reinterpret_cast<const float4*>(
        g_h3 + ((size_t)(b * NN + slot)) * 128) + c4;
    float4 h = *src;
    float m = mask[i];
    int c = c4 * 4;
    float4 y;
    y.x = fmaxf(fmaf(h.x, g_scale[c + 0], g_shift[c + 0]), 0.f) * m;
    y.y = fmaxf(fmaf(h.y, g_scale[c + 1], g_shift[c + 1]), 0.f) * m;
    y.z = fmaxf(fmaf(h.z, g_scale[c + 2], g_shift[c + 2]), 0.f) * m;
    y.w = fmaxf(fmaf(h.w, g_scale[c + 3], g_shift[c + 3]), 0.f) * m;
    reinterpret_cast<float4*>(out)[e] = y;
}

// ---------------- host ----------------
extern "C" void kernel_launch(void* const* d_in, const int* in_sizes, int n_in,
                              void* d_out, int out_size) {
    const float* xyz  = (const float*)d_in[0];
    const float* feat = (const float*)d_in[1];
    const float* mask = (const float*)d_in[2];
    const float* W1 = (const float*)d_in[3];
    const float* b1 = (const float*)d_in[4];
    const float* g1 = (const float*)d_in[5];
    const float* be1 = (const float*)d_in[6];
    const float* W2 = (const float*)d_in[7];
    const float* b2 = (const float*)d_in[8];
    const float* g2 = (const float*)d_in[9];
    const float* be2 = (const float*)d_in[10];
    const float* W3 = (const float*)d_in[11];
    const float* b3 = (const float*)d_in[12];
    const float* g3 = (const float*)d_in[13];
    const float* be3 = (const float*)d_in[14];
    float* out = (float*)d_out;

    void *p1, *p2, *p3, *x1, *x2, *x3, *w1, *w2, *w3;
    cudaGetSymbolAddress(&p1, g_h1);
    cudaGetSymbolAddress(&p2, g_h2);
    cudaGetSymbolAddress(&p3, g_h3);
    cudaGetSymbolAddress(&x1, g_x1);
    cudaGetSymbolAddress(&x2, g_x2);
    cudaGetSymbolAddress(&x3, g_x3);
    cudaGetSymbolAddress(&w1, g_w1);
    cudaGetSymbolAddress(&w2, g_w2);
    cudaGetSymbolAddress(&w3, g_w3);

    // dynamic smem: 1KB align slack + 2 pipeline buffers
    int sm1 = 1024 + 2 * (32768 + 32 * 128);        // 82944
    int sm2 = 1024 + 2 * (32768 + 64 * 128);        // 99328
    int sm3 = 1024 + 2 * (65536 + 128 * 128 * 2);   // 197632
    cudaFuncSetAttribute(conv_pipe<16, 32>,
                         cudaFuncAttributeMaxDynamicSharedMemorySize, sm1);
    cudaFuncSetAttribute(conv_pipe<32, 64>,
                         cudaFuncAttributeMaxDynamicSharedMemorySize, sm2);
    cudaFuncSetAttribute(conv_pipe<64, 128>,
                         cudaFuncAttributeMaxDynamicSharedMemorySize, sm3);

    k_zero<<<2048, 256>>>();
    k_wsplit<16, 32><<<(27 * 32 * 16 + 255) / 256, 256>>>(W1, (u16*)w1);
    k_wsplit<32, 64><<<(27 * 64 * 32 + 255) / 256, 256>>>(W2, (u16*)w2);
    k_wsplit<64, 128><<<(27 * 128 * 64 + 255) / 256, 256>>>(W3, (u16*)w3);
    k_min<<<512, 256>>>(xyz);
    k_codes<<<NPTS / 256, 256>>>(xyz);
    k_scanA<<<4096, 1024>>>();
    k_scanB<<<8, 512>>>();
    k_sumMb<<<1, 32>>>();
    k_scanC<<<4096, 1024>>>();
    k_aggregate<<<NPTS / 256, 256>>>(feat, mask);
    k_vnorm<<<NPTS / 256, 256>>>();
    k_nbr<<<dim3(NN / 128, BB), 128>>>();

    // layer 1: x1(16, split) -> h1(32)
    conv_pipe<16, 32><<<BB * 256, 256, sm1>>>((const u16*)x1, (float*)p1,
                                              (const u16*)w1, b1);
    k_zero_stats<<<1, 128>>>();
    k_stats<32><<<dim3(64, BB), 256>>>((const float*)p1);
    k_finalize<32><<<1, 32>>>(g1, be1);
    k_split<32><<<(NPTS * 8 + 255) / 256, 256>>>((const float*)p1, (u16*)x2);

    // layer 2: x2(32, split) -> h2(64)
    conv_pipe<32, 64><<<BB * 256, 256, sm2>>>((const u16*)x2, (float*)p2,
                                              (const u16*)w2, b2);
    k_zero_stats<<<1, 128>>>();
    k_stats<64><<<dim3(64, BB), 256>>>((const float*)p2);
    k_finalize<64><<<1, 64>>>(g2, be2);
    k_split<64><<<(NPTS * 16 + 255) / 256, 256>>>((const float*)p2, (u16*)x3);

    // layer 3: x3(64, split) -> h3(128)
    conv_pipe<64, 128><<<BB * 256, 256, sm3>>>((const u16*)x3, (float*)p3,
                                               (const u16*)w3, b3);
    k_zero_stats<<<1, 128>>>();
    k_stats<128><<<dim3(64, BB), 256>>>((const float*)p3);
    k_finalize<128><<<1, 128>>>(g3, be3);

    // scatter: out[point] = relu(bn3(h3[inv])) * mask
    k_final<<<(NPTS * 32 + 255) / 256, 256>>>(mask, out);
}

// round 9
// speedup vs baseline: 4.4019x; 1.2467x over previous
#include <cuda_runtime.h>
#include <cuda_fp16.h>
#include <cstdint>

typedef unsigned short u16;
typedef unsigned long long u64;

// Problem constants
#define BB    8
#define NN    65536
#define NPTS  (BB*NN)           // 524288
#define GSIZE (1<<21)           // 128^3 cells per batch
#define GTOT  (BB*GSIZE)        // 16,777,216

// ---------------- device scratch (static, no allocation) ----------------
__device__ int      g_grid[GTOT];
__device__ int      g_bsum[4096];
__device__ int      g_Mb[BB];
__device__ int      g_nvalid;
__device__ int      g_code[NPTS];
__device__ int      g_inv[NPTS];
__device__ int      g_slotcode[NPTS];
__device__ float    g_cnt[NPTS];
__device__ float    g_vfeat[(size_t)NPTS*16];
__device__ int      g_nbr[(size_t)NPTS*27];   // TRANSPOSED: [ko][b*NN+slot]
__device__ float    g_h1[(size_t)NPTS*32];
__device__ float    g_h2[(size_t)NPTS*64];
__device__ float    g_h3[(size_t)NPTS*128];
__device__ unsigned g_obits[3];
__device__ double   g_sum[128], g_sumsq[128];
__device__ float    g_scale[128], g_shift[128];
// pre-split hi/lo fp16 inputs per layer: voxel row = [hi CIN u16][lo CIN u16]
__device__ u16      g_x1[(size_t)NPTS*32];
__device__ u16      g_x2[(size_t)NPTS*64];
__device__ u16      g_x3[(size_t)NPTS*128];
// fp16 weights, pre-swizzled smem-image tiles: [27][COUT rows][64 u16 = 128B]
__device__ u16      g_w1[27*32*64];
__device__ u16      g_w2[27*64*64];
__device__ u16      g_w3[27*128*64];

// ---------------- ptx helpers ----------------
__device__ __forceinline__ uint32_t s2u(const void* p) {
    uint32_t a;
    asm("{ .reg .u64 t; cvta.to.shared.u64 t, %1; cvt.u32.u64 %0, t; }"
        : "=r"(a) : "l"(p));
    return a;
}
__device__ __forceinline__ void cpasync16(uint32_t dst, const void* src, uint32_t sz) {
    asm volatile("cp.async.cg.shared.global [%0], [%1], 16, %2;"
                 :: "r"(dst), "l"(src), "r"(sz) : "memory");
}
__device__ __forceinline__ void cpcommit() {
    asm volatile("cp.async.commit_group;" ::: "memory");
}
template <int N>
__device__ __forceinline__ void cpwait() {
    asm volatile("cp.async.wait_group %0;" :: "n"(N) : "memory");
}
__device__ __forceinline__ void ldmx4(uint32_t* r, uint32_t addr) {
    asm volatile("ldmatrix.sync.aligned.m8n8.x4.shared.b16 {%0,%1,%2,%3}, [%4];"
                 : "=r"(r[0]), "=r"(r[1]), "=r"(r[2]), "=r"(r[3]) : "r"(addr));
}
__device__ __forceinline__ void mma16816(float* d, const uint32_t* a,
                                         const uint32_t* b) {
    asm volatile(
        "mma.sync.aligned.m16n8k16.row.col.f32.f16.f16.f32 "
        "{%0,%1,%2,%3}, {%4,%5,%6,%7}, {%8,%9}, {%0,%1,%2,%3};"
        : "+f"(d[0]), "+f"(d[1]), "+f"(d[2]), "+f"(d[3])
        : "r"(a[0]), "r"(a[1]), "r"(a[2]), "r"(a[3]), "r"(b[0]), "r"(b[1]));
}
__device__ __forceinline__ uint32_t swz(uint32_t off) {
    return off ^ ((off >> 3) & 0x70);
}
__device__ __forceinline__ u16 f2h(float f) {
    __half h = __float2half_rn(f);
    return *reinterpret_cast<u16*>(&h);
}
__device__ __forceinline__ float h2f(u16 b) {
    __half h = *reinterpret_cast<__half*>(&b);
    return __half2float(h);
}

// ---------------- prologue helpers ----------------
__device__ __forceinline__ int blockExclScan(int val, int &total, int nwarps) {
    int lane = threadIdx.x & 31, wid = threadIdx.x >> 5;
    int v = val;
#pragma unroll
    for (int o = 1; o < 32; o <<= 1) {
        int t = __shfl_up_sync(0xffffffffu, v, o);
        if (lane >= o) v += t;
    }
    __shared__ int ws[32];
    if (lane == 31) ws[wid] = v;
    __syncthreads();
    if (wid == 0) {
        int w = (lane < nwarps) ? ws[lane] : 0;
#pragma unroll
        for (int o = 1; o < 32; o <<= 1) {
            int t = __shfl_up_sync(0xffffffffu, w, o);
            if (lane >= o) w += t;
        }
        ws[lane] = w;
    }
    __syncthreads();
    int warpoff = wid ? ws[wid - 1] : 0;
    total = ws[nwarps - 1];
    return warpoff + v - val;
}

// ---------------- prologue kernels ----------------
__global__ void k_zero() {
    size_t i = (size_t)blockIdx.x * blockDim.x + threadIdx.x;
    size_t stride = (size_t)gridDim.x * blockDim.x;
    for (size_t j = i; j < (size_t)GTOT; j += stride) g_grid[j] = 0;
    for (size_t j = i; j < (size_t)NPTS; j += stride) g_cnt[j] = 0.f;
    for (size_t j = i; j < (size_t)NPTS * 16; j += stride) g_vfeat[j] = 0.f;
    if (i < 3) g_obits[i] = 0x7F7FFFFFu;
}

__global__ void k_min(const float* __restrict__ xyz) {
    float mn0 = 3.4e38f, mn1 = 3.4e38f, mn2 = 3.4e38f;
    for (int i = blockIdx.x * blockDim.x + threadIdx.x; i < NPTS;
         i += gridDim.x * blockDim.x) {
        mn0 = fminf(mn0, xyz[3 * i + 0]);
        mn1 = fminf(mn1, xyz[3 * i + 1]);
        mn2 = fminf(mn2, xyz[3 * i + 2]);
    }
#pragma unroll
    for (int o = 16; o; o >>= 1) {
        mn0 = fminf(mn0, __shfl_down_sync(0xffffffffu, mn0, o));
        mn1 = fminf(mn1, __shfl_down_sync(0xffffffffu, mn1, o));
        mn2 = fminf(mn2, __shfl_down_sync(0xffffffffu, mn2, o));
    }
    __shared__ float s[3][8];
    int lane = threadIdx.x & 31, wid = threadIdx.x >> 5;
    if (lane == 0) { s[0][wid] = mn0; s[1][wid] = mn1; s[2][wid] = mn2; }
    __syncthreads();
    if (threadIdx.x == 0) {
        float a = s[0][0], b = s[1][0], c = s[2][0];
        for (int w = 1; w < 8; w++) {
            a = fminf(a, s[0][w]); b = fminf(b, s[1][w]); c = fminf(c, s[2][w]);
        }
        atomicMin(&g_obits[0], __float_as_uint(a));
        atomicMin(&g_obits[1], __float_as_uint(b));
        atomicMin(&g_obits[2], __float_as_uint(c));
    }
}

__global__ void k_codes(const float* __restrict__ xyz) {
    int i = blockIdx.x * blockDim.x + threadIdx.x;
    if (i >= NPTS) return;
    int b = i / NN;
    float ox = __uint_as_float(g_obits[0]);
    float oy = __uint_as_float(g_obits[1]);
    float oz = __uint_as_float(g_obits[2]);
    int vx = (int)__fdiv_rn(xyz[3 * i + 0] - ox, 0.4f);
    int vy = (int)__fdiv_rn(xyz[3 * i + 1] - oy, 0.4f);
    int vz = (int)__fdiv_rn(xyz[3 * i + 2] - oz, 0.4f);
    vx = min(127, max(0, vx)); vy = min(127, max(0, vy)); vz = min(127, max(0, vz));
    int code = vx | (vy << 7) | (vz << 14);
    g_code[i] = code;
    g_grid[(size_t)b * GSIZE + code] = 1;
}

__global__ void k_scanA() {
    int base = blockIdx.x * 4096 + threadIdx.x * 4;
    int s = g_grid[base] + g_grid[base + 1] + g_grid[base + 2] + g_grid[base + 3];
    int tot;
    blockExclScan(s, tot, 32);
    if (threadIdx.x == 0) g_bsum[blockIdx.x] = tot;
}

__global__ void k_scanB() {
    int b = blockIdx.x, t = threadIdx.x;
    int v = g_bsum[b * 512 + t];
    int tot;
    int excl = blockExclScan(v, tot, 16);
    g_bsum[b * 512 + t] = excl;
    if (t == 511) g_Mb[b] = tot;
}

__global__ void k_sumMb() {
    if (threadIdx.x == 0) {
        int s = 0;
        for (int b = 0; b < BB; b++) s += g_Mb[b];
        g_nvalid = s;
    }
}

__global__ void k_scanC() {
    int blk = blockIdx.x;
    int b = blk >> 9;
    int cbase = (blk & 511) * 4096 + threadIdx.x * 4;
    size_t gbase = (size_t)b * GSIZE + cbase;
    int o0 = g_grid[gbase + 0], o1 = g_grid[gbase + 1];
    int o2 = g_grid[gbase + 2], o3 = g_grid[gbase + 3];
    int s = o0 + o1 + o2 + o3;
    int tot;
    int excl = blockExclScan(s, tot, 32);
    int run = g_bsum[blk] + excl;
    int occ[4] = {o0, o1, o2, o3};
#pragma unroll
    for (int j = 0; j < 4; j++) {
        if (occ[j]) {
            g_grid[gbase + j] = run;
            g_slotcode[b * NN + run] = cbase + j;
            run++;
        } else {
            g_grid[gbase + j] = -1;
        }
    }
}

__global__ void k_aggregate(const float* __restrict__ feat,
                            const float* __restrict__ mask) {
    int i = blockIdx.x * blockDim.x + threadIdx.x;
    if (i >= NPTS) return;
    int b = i / NN;
    int code = g_code[i];
    int slot = g_grid[(size_t)b * GSIZE + code];
    g_inv[i] = slot;
    float m = mask[i];
    if (m != 0.f) {
        int row = b * NN + slot;
        atomicAdd(&g_cnt[row], m);
        const float* f = feat + (size_t)i * 16;
        float* dst = g_vfeat + (size_t)row * 16;
#pragma unroll
        for (int c = 0; c < 16; c++) atomicAdd(&dst[c], f[c] * m);
    }
}

// normalize voxel features and emit split fp16 hi/lo rows for conv1
__global__ void k_vnorm() {
    int i = blockIdx.x * blockDim.x + threadIdx.x;
    if (i >= NPTS) return;
    int b = i / NN, slot = i - b * NN;
    if (slot >= g_Mb[b]) return;
    float inv = 1.f / fmaxf(g_cnt[i], 1.f);
    const float* r = g_vfeat + (size_t)i * 16;
    u16* dst = g_x1 + (size_t)i * 32;
#pragma unroll
    for (int q = 0; q < 4; q++) {
        float4 x = *reinterpret_cast<const float4*>(r + 4 * q);
        x.x *= inv; x.y *= inv; x.z *= inv; x.w *= inv;
        u16 h0 = f2h(x.x), h1 = f2h(x.y), h2 = f2h(x.z), h3 = f2h(x.w);
        u16 l0 = f2h(x.x - h2f(h0)), l1 = f2h(x.y - h2f(h1));
        u16 l2 = f2h(x.z - h2f(h2)), l3 = f2h(x.w - h2f(h3));
        *reinterpret_cast<u64*>(dst + 4 * q) =
            (u64)h0 | ((u64)h1 << 16) | ((u64)h2 << 32) | ((u64)h3 << 48);
        *reinterpret_cast<u64*>(dst + 16 + 4 * q) =
            (u64)l0 | ((u64)l1 << 16) | ((u64)l2 << 32) | ((u64)l3 << 48);
    }
}

__global__ void k_nbr() {
    int slot = blockIdx.x * blockDim.x + threadIdx.x;
    int b = blockIdx.y;
    if (slot >= g_Mb[b]) return;
    int code = g_slotcode[b * NN + slot];
    int x = code & 127, y = (code >> 7) & 127, z = code >> 14;
    const int* grid = g_grid + (size_t)b * GSIZE;
    int row = b * NN + slot;
    int ko = 0;
    for (int dz = -1; dz <= 1; dz++)
        for (int dy = -1; dy <= 1; dy++)
            for (int dx = -1; dx <= 1; dx++, ko++) {
                int nx = x + dx, ny = y + dy, nz = z + dz;
                int r = -1;
                if ((unsigned)nx < 128u && (unsigned)ny < 128u && (unsigned)nz < 128u)
                    r = grid[nx | (ny << 7) | (nz << 14)];
                g_nbr[(size_t)ko * NPTS + row] = r;   // transposed layout
            }
}

// ---------------- weight rounding into swizzled fp16 smem-image tiles -----
template <int CIN, int COUT>
__global__ void k_wsplit(const float* __restrict__ W, u16* __restrict__ Wout) {
    int i = blockIdx.x * blockDim.x + threadIdx.x;
    if (i >= 27 * COUT * CIN) return;
    int cil = i % CIN;
    int co = (i / CIN) % COUT;
    int ko = i / (CIN * COUT);
    float w = W[(ko * CIN + cil) * COUT + co];
    size_t base = (size_t)ko * (COUT * 64);
    uint32_t off = swz((uint32_t)(co * 128 + cil * 2));
    Wout[base + off / 2] = f2h(w);
}

// ---------------- BN+ReLU + fp16 hi/lo split of a feature map ------------
template <int C>
__global__ void k_split(const float* __restrict__ in, u16* __restrict__ out) {
    int idx = blockIdx.x * blockDim.x + threadIdx.x;
    if (idx >= NPTS * (C / 4)) return;
    int v = idx / (C / 4);
    int q = idx - v * (C / 4);
    int c0 = 4 * q;
    float4 x = reinterpret_cast<const float4*>(in)[idx];
    x.x = fmaxf(fmaf(x.x, g_scale[c0 + 0], g_shift[c0 + 0]), 0.f);
    x.y = fmaxf(fmaf(x.y, g_scale[c0 + 1], g_shift[c0 + 1]), 0.f);
    x.z = fmaxf(fmaf(x.z, g_scale[c0 + 2], g_shift[c0 + 2]), 0.f);
    x.w = fmaxf(fmaf(x.w, g_scale[c0 + 3], g_shift[c0 + 3]), 0.f);
    u16 h0 = f2h(x.x), h1 = f2h(x.y), h2 = f2h(x.z), h3 = f2h(x.w);
    u16 l0 = f2h(x.x - h2f(h0)), l1 = f2h(x.y - h2f(h1));
    u16 l2 = f2h(x.z - h2f(h2)), l3 = f2h(x.w - h2f(h3));
    u16* row = out + (size_t)v * 2 * C;
    *reinterpret_cast<u64*>(row + c0) =
        (u64)h0 | ((u64)h1 << 16) | ((u64)h2 << 32) | ((u64)h3 << 48);
    *reinterpret_cast<u64*>(row + C + c0) =
        (u64)l0 | ((u64)l1 << 16) | ((u64)l2 << 32) | ((u64)l3 << 48);
}

// ---------------- cp.async-pipelined warp-MMA gather-conv, M=256 ----------
// 256-voxel tile per CTA; 8 warps each own 32 rows x full COUT. 2-deep
// cp.async pipeline. fp16 2-product scheme: D += xh*w + xl*w.
template <int CIN, int COUT>
__global__ void __launch_bounds__(256, (CIN == 64) ? 1 : 2)
conv_pipe(const u16* __restrict__ X, float* __restrict__ fout,
          const u16* __restrict__ Wg, const float* __restrict__ bias) {
    constexpr int CK = CIN / 16;
    constexpr int NT = COUT / 8;
    constexpr int NP = NT / 2;
    constexpr bool SPLIT = (CIN == 64);
    constexpr int ATILE = SPLIT ? 65536 : 32768;   // 256 rows x 128B (+lo subtile)
    constexpr int BTILE = COUT * 128;              // fp16 w tile
    constexpr int BUFSZ = ATILE + BTILE;
    constexpr int RB = 4 * CIN;          // gmem bytes per voxel row (hi+lo)
    constexpr int CPT = RB / 16;         // 16B chunks per row (1 thread/row)
    constexpr uint32_t LOA = SPLIT ? 32768u : (uint32_t)(CIN * 2);
    extern __shared__ char smem[];

    int blk = blockIdx.x;
    int b = blk >> 8, tilei = blk & 255;
    int Mb = g_Mb[b];
    int v0 = tilei * 256;
    if (v0 >= Mb) return;
    int tid = threadIdx.x, wid = tid >> 5, lane = tid & 31;

    uint32_t sbase = (s2u(smem) + 1023) & ~1023u;

    // staging: one thread per voxel row
    int gv = b * NN + v0 + tid;
    bool vok = (v0 + tid) < Mb;
    uint32_t arow = (uint32_t)tid * 128;

    // ldmatrix lane bases
    uint32_t a_off0 = (uint32_t)(wid * 32 + (lane & 15)) * 128 + (lane >> 4) * 16;
    uint32_t b_off0 = (uint32_t)((lane >> 4) * 8 + (lane & 7)) * 128 +
                      ((lane >> 3) & 1) * 16;

    float d[2][NT][4];
#pragma unroll
    for (int mt = 0; mt < 2; mt++)
#pragma unroll
        for (int nt = 0; nt < NT; nt++)
#pragma unroll
            for (int j = 0; j < 4; j++) d[mt][nt][j] = 0.f;

    const u16* Xb = X + (size_t)b * NN * (RB / 2);

    auto stage = [&](int ko, int buf, int nbr) {
        uint32_t sB = sbase + buf * BUFSZ + ATILE;
        const char* wsrc = (const char*)Wg + (size_t)ko * BTILE;
#pragma unroll
        for (int e = 0; e < BTILE / 16 / 256; e++) {
            int idx = tid + e * 256;
            cpasync16(sB + idx * 16, wsrc + idx * 16, 16);
        }
        uint32_t sA = sbase + buf * BUFSZ;
        uint32_t sz = (nbr >= 0) ? 16u : 0u;
        const char* xs = (const char*)(Xb + (size_t)max(nbr, 0) * (RB / 2));
#pragma unroll
        for (int j = 0; j < CPT; j++) {
            uint32_t doff = SPLIT
                ? (((j >= 8) ? 32768u : 0u) + swz(arow + (j & 7) * 16))
                : swz(arow + (uint32_t)j * 16);
            cpasync16(sA + doff, xs + j * 16, sz);
        }
    };

    auto compute = [&](int buf) {
        uint32_t sA = sbase + buf * BUFSZ;
        uint32_t sB = sA + ATILE;
#pragma unroll
        for (int kc = 0; kc < CK; kc++) {
            uint32_t ah[2][4], al[2][4];
#pragma unroll
            for (int mt = 0; mt < 2; mt++) {
                uint32_t ao = a_off0 + (uint32_t)mt * 16 * 128 + kc * 32;
                ldmx4(ah[mt], sA + swz(ao));
                ldmx4(al[mt], sA + swz(ao + LOA));
            }
#pragma unroll
            for (int p = 0; p < NP; p++) {
                uint32_t bh[4];
                ldmx4(bh, sB + swz(b_off0 + p * 2048 + kc * 32));
#pragma unroll
                for (int mt = 0; mt < 2; mt++) {
                    mma16816(d[mt][2 * p],     ah[mt], bh);
                    mma16816(d[mt][2 * p + 1], ah[mt], bh + 2);
                    mma16816(d[mt][2 * p],     al[mt], bh);
                    mma16816(d[mt][2 * p + 1], al[mt], bh + 2);
                }
            }
        }
    };

    int nbr_c = vok ? __ldg(&g_nbr[gv]) : -1;               // tap 0
    stage(0, 0, nbr_c);
    cpcommit();
    int nbr_n = vok ? __ldg(&g_nbr[(size_t)NPTS + gv]) : -1; // tap 1
    for (int ko = 0; ko < 27; ko++) {
        int nxt = ko + 1;
        if (nxt < 27) {
            stage(nxt, nxt & 1, nbr_n);
            cpcommit();
            nbr_n = (vok && nxt + 1 < 27)
                ? __ldg(&g_nbr[(size_t)(nxt + 1) * NPTS + gv]) : -1;
            cpwait<1>();
        } else {
            cpwait<0>();
        }
        __syncthreads();
        compute(ko & 1);
        __syncthreads();   // buffer (ko&1) free for restage at iter ko+1
    }

    // epilogue: D regs -> gmem (+bias)
    int col0 = (lane & 3) * 2;
#pragma unroll
    for (int mt = 0; mt < 2; mt++) {
        int m0 = v0 + wid * 32 + mt * 16 + (lane >> 2);
        bool ok0 = m0 < Mb, ok1 = (m0 + 8) < Mb;
        float* dst0 = fout + ((size_t)(b * NN + m0)) * COUT;
        float* dst1 = dst0 + (size_t)8 * COUT;
#pragma unroll
        for (int nt = 0; nt < NT; nt++) {
            int c = nt * 8 + col0;
            float bx = bias[c], by = bias[c + 1];
            if (ok0)
                *reinterpret_cast<float2*>(dst0 + c) =
                    make_float2(d[mt][nt][0] + bx, d[mt][nt][1] + by);
            if (ok1)
                *reinterpret_cast<float2*>(dst1 + c) =
                    make_float2(d[mt][nt][2] + bx, d[mt][nt][3] + by);
        }
    }
}

// ---------------- BN stats / finalize / output ---------------------------
__global__ void k_zero_stats() {
    int t = threadIdx.x;
    if (t < 128) { g_sum[t] = 0.0; g_sumsq[t] = 0.0; }
}

template <int COUT>
__global__ void k_stats(const float* __restrict__ f) {
    constexpr int RP = 256 / COUT;
    int b = blockIdx.y;
    int Mb = g_Mb[b];
    int tid = threadIdx.x;
    int c = tid % COUT, r0 = tid / COUT;
    float s = 0.f, s2 = 0.f;
    for (int v = blockIdx.x * RP + r0; v < Mb; v += gridDim.x * RP) {
        float x = f[((size_t)(b * NN + v)) * COUT + c];
        s += x;
        s2 = fmaf(x, x, s2);
    }
    __shared__ float sh[256], sh2[256];
    sh[tid] = s; sh2[tid] = s2;
    __syncthreads();
    for (int st = 128; st >= COUT; st >>= 1) {
        if (tid < st) { sh[tid] += sh[tid + st]; sh2[tid] += sh2[tid + st]; }
        __syncthreads();
    }
    if (tid < COUT) {
        atomicAdd(&g_sum[tid], (double)sh[tid]);
        atomicAdd(&g_sumsq[tid], (double)sh2[tid]);
    }
}

template <int COUT>
__global__ void k_finalize(const float* __restrict__ gamma,
                           const float* __restrict__ beta) {
    int c = threadIdx.x;
    if (c >= COUT) return;
    double n = (double)g_nvalid;
    if (n < 1.0) n = 1.0;
    double mean = g_sum[c] / n;
    double var = g_sumsq[c] / n - mean * mean;
    if (var < 0.0) var = 0.0;
    float a = (float)((double)gamma[c] / sqrt(var + 1e-5));
    g_scale[c] = a;
    g_shift[c] = beta[c] - (float)mean * a;
}

__global__ void k_final(const float* __restrict__ mask, float* __restrict__ out) {
    size_t e = (size_t)blockIdx.x * blockDim.x + threadIdx.x;  // per float4
    if (e >= (size_t)NPTS * 32) return;
    int i = (int)(e >> 5);
    int c4 = (int)(e & 31);
    int b = i / NN;
    int slot = g_inv[i];
    const float4* src = reinterpret_cast<const float4*>(
        g_h3 + ((size_t)(b * NN + slot)) * 128) + c4;
    float4 h = *src;
    float m = mask[i];
    int c = c4 * 4;
    float4 y;
    y.x = fmaxf(fmaf(h.x, g_scale[c + 0], g_shift[c + 0]), 0.f) * m;
    y.y = fmaxf(fmaf(h.y, g_scale[c + 1], g_shift[c + 1]), 0.f) * m;
    y.z = fmaxf(fmaf(h.z, g_scale[c + 2], g_shift[c + 2]), 0.f) * m;
    y.w = fmaxf(fmaf(h.w, g_scale[c + 3], g_shift[c + 3]), 0.f) * m;
    reinterpret_cast<float4*>(out)[e] = y;
}

// ---------------- host ----------------
extern "C" void kernel_launch(void* const* d_in, const int* in_sizes, int n_in,
                              void* d_out, int out_size) {
    const float* xyz  = (const float*)d_in[0];
    const float* feat = (const float*)d_in[1];
    const float* mask = (const float*)d_in[2];
    const float* W1 = (const float*)d_in[3];
    const float* b1 = (const float*)d_in[4];
    const float* g1 = (const float*)d_in[5];
    const float* be1 = (const float*)d_in[6];
    const float* W2 = (const float*)d_in[7];
    const float* b2 = (const float*)d_in[8];
    const float* g2 = (const float*)d_in[9];
    const float* be2 = (const float*)d_in[10];
    const float* W3 = (const float*)d_in[11];
    const float* b3 = (const float*)d_in[12];
    const float* g3 = (const float*)d_in[13];
    const float* be3 = (const float*)d_in[14];
    float* out = (float*)d_out;

    void *p1, *p2, *p3, *x1, *x2, *x3, *w1, *w2, *w3;
    cudaGetSymbolAddress(&p1, g_h1);
    cudaGetSymbolAddress(&p2, g_h2);
    cudaGetSymbolAddress(&p3, g_h3);
    cudaGetSymbolAddress(&x1, g_x1);
    cudaGetSymbolAddress(&x2, g_x2);
    cudaGetSymbolAddress(&x3, g_x3);
    cudaGetSymbolAddress(&w1, g_w1);
    cudaGetSymbolAddress(&w2, g_w2);
    cudaGetSymbolAddress(&w3, g_w3);

    // dynamic smem: 1KB align slack + 2 pipeline buffers
    int sm1 = 1024 + 2 * (32768 + 32 * 128);    // 82944
    int sm2 = 1024 + 2 * (32768 + 64 * 128);    // 99328
    int sm3 = 1024 + 2 * (65536 + 128 * 128);   // 164864
    cudaFuncSetAttribute(conv_pipe<16, 32>,
                         cudaFuncAttributeMaxDynamicSharedMemorySize, sm1);
    cudaFuncSetAttribute(conv_pipe<32, 64>,
                         cudaFuncAttributeMaxDynamicSharedMemorySize, sm2);
    cudaFuncSetAttribute(conv_pipe<64, 128>,
                         cudaFuncAttributeMaxDynamicSharedMemorySize, sm3);

    k_zero<<<2048, 256>>>();
    k_wsplit<16, 32><<<(27 * 32 * 16 + 255) / 256, 256>>>(W1, (u16*)w1);
    k_wsplit<32, 64><<<(27 * 64 * 32 + 255) / 256, 256>>>(W2, (u16*)w2);
    k_wsplit<64, 128><<<(27 * 128 * 64 + 255) / 256, 256>>>(W3, (u16*)w3);
    k_min<<<512, 256>>>(xyz);
    k_codes<<<NPTS / 256, 256>>>(xyz);
    k_scanA<<<4096, 1024>>>();
    k_scanB<<<8, 512>>>();
    k_sumMb<<<1, 32>>>();
    k_scanC<<<4096, 1024>>>();
    k_aggregate<<<NPTS / 256, 256>>>(feat, mask);
    k_vnorm<<<NPTS / 256, 256>>>();
    k_nbr<<<dim3(NN / 128, BB), 128>>>();

    // layer 1: x1(16, split) -> h1(32)
    conv_pipe<16, 32><<<BB * 256, 256, sm1>>>((const u16*)x1, (float*)p1,
                                              (const u16*)w1, b1);
    k_zero_stats<<<1, 128>>>();
    k_stats<32><<<dim3(64, BB), 256>>>((const float*)p1);
    k_finalize<32><<<1, 32>>>(g1, be1);
    k_split<32><<<(NPTS * 8 + 255) / 256, 256>>>((const float*)p1, (u16*)x2);

    // layer 2: x2(32, split) -> h2(64)
    conv_pipe<32, 64><<<BB * 256, 256, sm2>>>((const u16*)x2, (float*)p2,
                                              (const u16*)w2, b2);
    k_zero_stats<<<1, 128>>>();
    k_stats<64><<<dim3(64, BB), 256>>>((const float*)p2);
    k_finalize<64><<<1, 64>>>(g2, be2);
    k_split<64><<<(NPTS * 16 + 255) / 256, 256>>>((const float*)p2, (u16*)x3);

    // layer 3: x3(64, split) -> h3(128)
    conv_pipe<64, 128><<<BB * 256, 256, sm3>>>((const u16*)x3, (float*)p3,
                                               (const u16*)w3, b3);
    k_zero_stats<<<1, 128>>>();
    k_stats<128><<<dim3(64, BB), 256>>>((const float*)p3);
    k_finalize<128><<<1, 128>>>(g3, be3);

    // scatter: out[point] = relu(bn3(h3[inv])) * mask
    k_final<<<(NPTS * 32 + 255) / 256, 256>>>(mask, out);
}